// round 7
// baseline (speedup 1.0000x reference)
#include <cuda_runtime.h>
#include <cuda_bf16.h>
#include <math.h>

#define NKV   32768
#define NQ    4096
#define CDIM  256
#define KSEL  100
#define NT    512
#define QB    2
#define CAP   2048
#define SSAMP 1024   // sample size for threshold estimation
#define MSEL  16     // 16th-smallest sample key -> threshold (upper bucket edge)

// Packed k_pos: {x, y, z, |k|^2}. Written by pack_kpos each launch. 512 KB, L2-hot.
__device__ float4 g_kp4[NKV];

struct Smem {
    uint2    cand[QB][CAP];    // 32 KB {key, idx}; overlaid by sample keys first
    float4   part4[QB][256];   // 8 KB  AV partial sums (4 groups x 64 float4)
    float    attn[QB][128];    // 1 KB
    int      ids[QB][128];     // 1 KB
    unsigned hist[256];        // 1 KB
    int      warpsum[8];
    int      red_min[16];
    float    red1[16], red2[16];
    int      cnt_low[QB], cnt_c[QB];
    int      s_bucket, s_kneed, s_m;
    float    s_sum[QB], s_sumsq[QB];
};

// Canonical key pieces — identical fmaf chains everywhere => bit-identical keys.
__device__ __forceinline__ float k_sk(float kx, float ky, float kz) {
    return fmaf(kx, kx, fmaf(ky, ky, kz * kz));
}
__device__ __forceinline__ float k_dot(float kx, float ky, float kz,
                                       float qx, float qy, float qz) {
    return fmaf(qx, kx, fmaf(qy, ky, qz * kz));
}
// Packed form: p.w == k_sk(p.x,p.y,p.z) (written by pack_kpos with the same chain).
__device__ __forceinline__ float pk_d2u(float4 p, float qx, float qy, float qz, float sqn) {
    return fmaf(-2.0f, k_dot(p.x, p.y, p.z, qx, qy, qz), sqn + p.w);   // unclamped
}
__device__ __forceinline__ unsigned k_key(float d2u) {
    return __float_as_uint(fmaxf(d2u, 0.0f));
}

__global__ void pack_kpos(const float* __restrict__ k_pos) {
    const int i = blockIdx.x * blockDim.x + threadIdx.x;
    if (i < NKV) {
        const float kx = k_pos[3 * i + 0];
        const float ky = k_pos[3 * i + 1];
        const float kz = k_pos[3 * i + 2];
        g_kp4[i] = make_float4(kx, ky, kz, k_sk(kx, ky, kz));
    }
}

// All 512 threads enter. Picks bucket containing the kcur-th smallest;
// results broadcast in sm->s_bucket / sm->s_kneed (valid after return).
__device__ __forceinline__ void pick_bucket(Smem* sm, int kcur, int tid, int lane) {
    int v = 0, incl = 0;
    if (tid < 256) {
        v = (int)sm->hist[tid];
        incl = v;
        #pragma unroll
        for (int o = 1; o < 32; o <<= 1) {
            int y = __shfl_up_sync(0xffffffffu, incl, o);
            if (lane >= o) incl += y;
        }
        if (lane == 31) sm->warpsum[tid >> 5] = incl;
    }
    __syncthreads();
    if (tid < 8) {
        int x = sm->warpsum[tid];
        #pragma unroll
        for (int o = 1; o < 8; o <<= 1) {
            int y = __shfl_up_sync(0xffu, x, o);
            if (tid >= o) x += y;
        }
        sm->warpsum[tid] = x;
    }
    __syncthreads();
    if (tid < 256) {
        const int w   = tid >> 5;
        const int tot = incl + (w ? sm->warpsum[w - 1] : 0);
        const int exc = tot - v;
        if (exc < kcur && tot >= kcur) {   // exactly one thread true
            sm->s_bucket = tid;
            sm->s_kneed  = kcur - exc;
        }
    }
    __syncthreads();
}

__global__ __launch_bounds__(NT, 4)
void sparse_attn_kernel(const float* __restrict__ q_feat,
                        const float* __restrict__ k_feat,
                        const float* __restrict__ v_feat,
                        const float* __restrict__ q_pos,
                        const float* __restrict__ gamma,
                        const float* __restrict__ beta,
                        float* __restrict__ out)
{
    extern __shared__ unsigned char smem_raw[];
    Smem* sm = reinterpret_cast<Smem*>(smem_raw);
    const int tid  = threadIdx.x;
    const int lane = tid & 31;
    const int warp = tid >> 5;
    const int qbase = blockIdx.x * QB;

    float qx[QB], qy[QB], qz[QB], sqn[QB];
    #pragma unroll
    for (int qi = 0; qi < QB; ++qi) {
        qx[qi] = q_pos[3 * (qbase + qi) + 0];
        qy[qi] = q_pos[3 * (qbase + qi) + 1];
        qz[qi] = q_pos[3 * (qbase + qi) + 2];
        sqn[qi] = fmaf(qx[qi], qx[qi], fmaf(qy[qi], qy[qi], qz[qi] * qz[qi]));
    }
    if (tid == 0) {
        sm->cnt_low[0] = sm->cnt_low[1] = 0;
        sm->cnt_c[0]   = sm->cnt_c[1]   = 0;
    }

    // ---------------- Phase 0: sample keys (first SSAMP points) -------------
    unsigned* samp = (unsigned*)&sm->cand[0][0];   // SSAMP keys/query, overlaid
    if (tid < SSAMP / 4) {                          // 256 threads x 4 points
        const float4 p0 = g_kp4[4 * tid + 0];
        const float4 p1 = g_kp4[4 * tid + 1];
        const float4 p2 = g_kp4[4 * tid + 2];
        const float4 p3 = g_kp4[4 * tid + 3];
        #pragma unroll
        for (int qi = 0; qi < QB; ++qi) {
            uint4 kk;
            kk.x = k_key(pk_d2u(p0, qx[qi], qy[qi], qz[qi], sqn[qi]));
            kk.y = k_key(pk_d2u(p1, qx[qi], qy[qi], qz[qi], sqn[qi]));
            kk.z = k_key(pk_d2u(p2, qx[qi], qy[qi], qz[qi], sqn[qi]));
            kk.w = k_key(pk_d2u(p3, qx[qi], qy[qi], qz[qi], sqn[qi]));
            ((uint4*)samp)[qi * (SSAMP / 4) + tid] = kk;
        }
    }
    __syncthreads();

    // ---------------- Phase 1: 2-pass radix on samples -> threshold t0 ------
    // Upper edge of the 16-bit bucket of the MSEL-th smallest sample key.
    // Superset admission is always safe (exact refine + fallback below).
    float t0f[QB];
    #pragma unroll
    for (int qi = 0; qi < QB; ++qi) {
        unsigned prefval = 0u, prefmask = 0u;
        int kneed = MSEL;
        #pragma unroll
        for (int pass = 0; pass < 2; ++pass) {
            const int shift = 24 - 8 * pass;
            if (tid < 256) sm->hist[tid] = 0u;
            __syncthreads();
            #pragma unroll
            for (int it = 0; it < SSAMP / NT; ++it) {
                const unsigned key = samp[qi * SSAMP + tid + it * NT];
                if ((key & prefmask) == prefval)
                    atomicAdd(&sm->hist[(key >> shift) & 0xFFu], 1u);
            }
            __syncthreads();
            pick_bucket(sm, kneed, tid, lane);
            prefval  |= ((unsigned)sm->s_bucket) << shift;
            kneed     = sm->s_kneed;
            prefmask |= 0xFFu << shift;
            __syncthreads();
        }
        t0f[qi] = __uint_as_float(prefval | 0x0000FFFFu);   // bucket upper edge, >= 0
    }
    __syncthreads();   // done reading samp; cand may now be written

    // ---------------- Phase 2: single full scan (4 points/thread/iter) ------
    // (clamped_key <= t0u) <=> (d2u <= t0f) since t0f >= 0.
    #pragma unroll 1
    for (int j = tid; j < NKV / 4; j += NT) {               // 16 iterations
        const float4 p0 = g_kp4[4 * j + 0];
        const float4 p1 = g_kp4[4 * j + 1];
        const float4 p2 = g_kp4[4 * j + 2];
        const float4 p3 = g_kp4[4 * j + 3];
        #pragma unroll
        for (int qi = 0; qi < QB; ++qi) {
            const float d0 = pk_d2u(p0, qx[qi], qy[qi], qz[qi], sqn[qi]);
            const float d1 = pk_d2u(p1, qx[qi], qy[qi], qz[qi], sqn[qi]);
            const float d2 = pk_d2u(p2, qx[qi], qy[qi], qz[qi], sqn[qi]);
            const float d3 = pk_d2u(p3, qx[qi], qy[qi], qz[qi], sqn[qi]);
            if (d0 <= t0f[qi]) {
                const int p = atomicAdd(&sm->cnt_c[qi], 1);
                if (p < CAP) sm->cand[qi][p] = make_uint2(k_key(d0), (unsigned)(4 * j + 0));
            }
            if (d1 <= t0f[qi]) {
                const int p = atomicAdd(&sm->cnt_c[qi], 1);
                if (p < CAP) sm->cand[qi][p] = make_uint2(k_key(d1), (unsigned)(4 * j + 1));
            }
            if (d2 <= t0f[qi]) {
                const int p = atomicAdd(&sm->cnt_c[qi], 1);
                if (p < CAP) sm->cand[qi][p] = make_uint2(k_key(d2), (unsigned)(4 * j + 2));
            }
            if (d3 <= t0f[qi]) {
                const int p = atomicAdd(&sm->cnt_c[qi], 1);
                if (p < CAP) sm->cand[qi][p] = make_uint2(k_key(d3), (unsigned)(4 * j + 3));
            }
        }
    }
    __syncthreads();

    // ---------------- Phase 3: exact top-KSEL per query ---------------------
    #pragma unroll
    for (int qi = 0; qi < QB; ++qi) {
        const int nc0 = sm->cnt_c[qi];
        unsigned T;
        int kneed;

        if (nc0 >= KSEL && nc0 <= CAP) {
            // ---- refine within <= CAP candidates: full 32-bit radix select --
            const int nc = nc0;
            unsigned prefval = 0u, prefmask = 0u;
            kneed = KSEL;
            #pragma unroll
            for (int pass = 0; pass < 4; ++pass) {
                const int shift = 24 - 8 * pass;
                if (tid < 256) sm->hist[tid] = 0u;
                __syncthreads();
                for (int j = tid; j < nc; j += NT) {
                    const unsigned key = sm->cand[qi][j].x;
                    if ((key & prefmask) == prefval)
                        atomicAdd(&sm->hist[(key >> shift) & 0xFFu], 1u);
                }
                __syncthreads();
                pick_bucket(sm, kneed, tid, lane);
                prefval  |= ((unsigned)sm->s_bucket) << shift;
                kneed     = sm->s_kneed;
                prefmask |= 0xFFu << shift;
                __syncthreads();
            }
            T = prefval;
            // strictly-less keys -> ids (order irrelevant: softmax perm-invariant)
            for (int j = tid; j < nc; j += NT) {
                const uint2 c = sm->cand[qi][j];
                if (c.x < T) {
                    const int p = atomicAdd(&sm->cnt_low[qi], 1);
                    sm->ids[qi][p] = (int)c.y;
                }
            }
            __syncthreads();
            // ties at T: kneed smallest indices (jax top_k stability)
            const int base = sm->cnt_low[qi];
            int last = -1;
            for (int t2 = 0; t2 < kneed; ++t2) {
                int local = 0x7fffffff;
                for (int j = tid; j < nc; j += NT) {
                    const uint2 c = sm->cand[qi][j];
                    if (c.x == T && (int)c.y > last) local = min(local, (int)c.y);
                }
                #pragma unroll
                for (int o = 16; o; o >>= 1)
                    local = min(local, __shfl_xor_sync(0xffffffffu, local, o));
                if (lane == 0) sm->red_min[warp] = local;
                __syncthreads();
                if (tid == 0) {
                    int m = 0x7fffffff;
                    #pragma unroll
                    for (int w = 0; w < NT / 32; ++w) m = min(m, sm->red_min[w]);
                    sm->ids[qi][base + t2] = m;
                    sm->s_m = m;
                }
                __syncthreads();
                last = sm->s_m;
                __syncthreads();
            }
        } else {
            // ---- fallback: exact full-rescan radix select (rare) ------------
            unsigned prefval = 0u, prefmask = 0u;
            kneed = KSEL;
            for (int pass = 0; pass < 4; ++pass) {
                const int shift = 24 - 8 * pass;
                if (tid < 256) sm->hist[tid] = 0u;
                __syncthreads();
                for (int i = tid; i < NKV; i += NT) {
                    const unsigned key = k_key(pk_d2u(g_kp4[i], qx[qi], qy[qi], qz[qi], sqn[qi]));
                    if ((key & prefmask) == prefval)
                        atomicAdd(&sm->hist[(key >> shift) & 0xFFu], 1u);
                }
                __syncthreads();
                pick_bucket(sm, kneed, tid, lane);
                prefval  |= ((unsigned)sm->s_bucket) << shift;
                kneed     = sm->s_kneed;
                prefmask |= 0xFFu << shift;
                __syncthreads();
            }
            T = prefval;
            if (tid == 0) sm->cnt_low[qi] = 0;
            __syncthreads();
            for (int i = tid; i < NKV; i += NT) {
                const unsigned key = k_key(pk_d2u(g_kp4[i], qx[qi], qy[qi], qz[qi], sqn[qi]));
                if (key < T) {
                    const int p = atomicAdd(&sm->cnt_low[qi], 1);
                    sm->ids[qi][p] = i;
                }
            }
            __syncthreads();
            const int base = sm->cnt_low[qi];
            int last = -1;
            for (int t2 = 0; t2 < kneed; ++t2) {
                int local = 0x7fffffff;
                for (int i = tid; i < NKV; i += NT) {
                    const unsigned key = k_key(pk_d2u(g_kp4[i], qx[qi], qy[qi], qz[qi], sqn[qi]));
                    if (key == T && i > last) local = min(local, i);
                }
                #pragma unroll
                for (int o = 16; o; o >>= 1)
                    local = min(local, __shfl_xor_sync(0xffffffffu, local, o));
                if (lane == 0) sm->red_min[warp] = local;
                __syncthreads();
                if (tid == 0) {
                    int m = 0x7fffffff;
                    #pragma unroll
                    for (int w = 0; w < NT / 32; ++w) m = min(m, sm->red_min[w]);
                    sm->ids[qi][base + t2] = m;
                    sm->s_m = m;
                }
                __syncthreads();
                last = sm->s_m;
                __syncthreads();
            }
        }
        __syncthreads();
    }

    // ---------------- Phase 4: attention logits + softmax --------------------
    // q row cached in registers (2 x float4 per lane); warps 0-7 -> q0, 8-15 -> q1.
    const int wq = warp >> 3;
    const int wl = warp & 7;
    {
        const float4* qrow = (const float4*)(q_feat + (long)(qbase + wq) * CDIM);
        const float4 qa = qrow[lane];
        const float4 qb = qrow[lane + 32];
        for (int n = wl; n < KSEL; n += 8) {
            const float4* kr4 = (const float4*)(k_feat + (long)sm->ids[wq][n] * CDIM);
            const float4 ka = kr4[lane];
            const float4 kb = kr4[lane + 32];
            float s = 0.f;
            s = fmaf(qa.x, ka.x, s); s = fmaf(qa.y, ka.y, s);
            s = fmaf(qa.z, ka.z, s); s = fmaf(qa.w, ka.w, s);
            s = fmaf(qb.x, kb.x, s); s = fmaf(qb.y, kb.y, s);
            s = fmaf(qb.z, kb.z, s); s = fmaf(qb.w, kb.w, s);
            #pragma unroll
            for (int o = 16; o; o >>= 1) s += __shfl_xor_sync(0xffffffffu, s, o);
            if (lane == 0) sm->attn[wq][n] = s * 0.0625f;   // C^-0.5 = 1/16
        }
    }
    __syncthreads();

    if ((warp & 7) == 0) {              // warp 0 -> q0, warp 8 -> q1
        const int qi = wq;
        float m = -1e30f;
        for (int n = lane; n < KSEL; n += 32) m = fmaxf(m, sm->attn[qi][n]);
        #pragma unroll
        for (int o = 16; o; o >>= 1) m = fmaxf(m, __shfl_xor_sync(0xffffffffu, m, o));
        float ssum = 0.f;
        for (int n = lane; n < KSEL; n += 32) {
            const float e = __expf(sm->attn[qi][n] - m);
            sm->attn[qi][n] = e;
            ssum += e;
        }
        #pragma unroll
        for (int o = 16; o; o >>= 1) ssum += __shfl_xor_sync(0xffffffffu, ssum, o);
        const float inv = 1.f / ssum;
        for (int n = lane; n < KSEL; n += 32) sm->attn[qi][n] *= inv;
    }
    __syncthreads();

    // ---------------- Phase 5: x = attn @ V (float4, 4 groups/query) --------
    {
        const int qi = tid >> 8;           // query
        const int g  = (tid >> 6) & 3;     // group 0..3 (25 neighbors each)
        const int t  = tid & 63;           // 64 threads x float4 = 256 channels
        float4 acc = make_float4(0.f, 0.f, 0.f, 0.f);
        for (int n = g; n < KSEL; n += 4) {
            const float w  = sm->attn[qi][n];
            const float4 v4 = *(const float4*)(v_feat + (long)sm->ids[qi][n] * CDIM + t * 4);
            acc.x = fmaf(w, v4.x, acc.x);
            acc.y = fmaf(w, v4.y, acc.y);
            acc.z = fmaf(w, v4.z, acc.z);
            acc.w = fmaf(w, v4.w, acc.w);
        }
        sm->part4[qi][g * 64 + t] = acc;
    }
    __syncthreads();

    // ---------------- Phase 6: combine partials; y = 2x; LayerNorm ----------
    {
        const int qi = tid >> 8;
        const int c  = tid & 255;
        const float* pf = (const float*)&sm->part4[qi][0];
        const float y = 2.0f * ((pf[c] + pf[256 + c]) + (pf[512 + c] + pf[768 + c]));

        float s1 = y, s2 = y * y;
        #pragma unroll
        for (int o = 16; o; o >>= 1) {
            s1 += __shfl_xor_sync(0xffffffffu, s1, o);
            s2 += __shfl_xor_sync(0xffffffffu, s2, o);
        }
        if (lane == 0) { sm->red1[warp] = s1; sm->red2[warp] = s2; }
        __syncthreads();
        if ((tid & 255) == 0) {
            float a = 0.f, b = 0.f;
            #pragma unroll
            for (int w = 0; w < 8; ++w) {
                a += sm->red1[qi * 8 + w];
                b += sm->red2[qi * 8 + w];
            }
            sm->s_sum[qi] = a; sm->s_sumsq[qi] = b;
        }
        __syncthreads();
        const float mean = sm->s_sum[qi] * (1.0f / CDIM);
        const float var  = sm->s_sumsq[qi] * (1.0f / CDIM) - mean * mean;
        const float r    = rsqrtf(var + 1e-5f);
        out[(long)(qbase + qi) * CDIM + c] = (y - mean) * r * gamma[c] + beta[c];
    }
}

extern "C" void kernel_launch(void* const* d_in, const int* in_sizes, int n_in,
                              void* d_out, int out_size)
{
    // metadata order: res_feat, q_feat, k_feat, v_feat, q_pos, k_pos, gamma, beta
    // res_feat (d_in[0]) is mathematically dead: full scatter overwrite -> y = 2x.
    const float* q_feat = (const float*)d_in[1];
    const float* k_feat = (const float*)d_in[2];
    const float* v_feat = (const float*)d_in[3];
    const float* q_pos  = (const float*)d_in[4];
    const float* k_pos  = (const float*)d_in[5];
    const float* gamma  = (const float*)d_in[6];
    const float* beta   = (const float*)d_in[7];
    float* out = (float*)d_out;

    (void)in_sizes; (void)n_in; (void)out_size;

    pack_kpos<<<NKV / 256, 256>>>(k_pos);

    cudaFuncSetAttribute(sparse_attn_kernel,
                         cudaFuncAttributeMaxDynamicSharedMemorySize,
                         (int)sizeof(Smem));
    sparse_attn_kernel<<<NQ / QB, NT, sizeof(Smem)>>>(
        q_feat, k_feat, v_feat, q_pos, gamma, beta, out);
}

// round 8
// speedup vs baseline: 1.3433x; 1.3433x over previous
#include <cuda_runtime.h>
#include <cuda_bf16.h>
#include <math.h>

#define NKV   32768
#define NQ    4096
#define CDIM  256
#define KSEL  100
#define NT    512
#define QB    2
#define CAP   2048
#define SSAMP 1024   // sample size for threshold estimation
#define MSEL  16     // 16th-smallest sample key -> threshold (upper bucket edge)

// SoA packed k_pos (coalesced float4 loads): x, y, z, |k|^2. 512 KB total, L2-hot.
__device__ float g_sx[NKV];
__device__ float g_sy[NKV];
__device__ float g_sz[NKV];
__device__ float g_sw[NKV];

struct Smem {
    uint2    cand[QB][CAP];    // 32 KB {key, idx}; overlaid by sample keys first
    float4   part4[QB][256];   // 8 KB  AV partial sums (4 groups x 64 float4)
    float    attn[QB][128];    // 1 KB
    int      ids[QB][128];     // 1 KB
    unsigned hist[256];        // 1 KB
    int      warpsum[8];
    int      red_min[16];
    float    red1[16], red2[16];
    int      cnt_low[QB], cnt_c[QB];
    int      s_bucket, s_kneed, s_m;
    float    s_sum[QB], s_sumsq[QB];
};

// Canonical key pieces — identical fmaf chains everywhere => bit-identical keys.
__device__ __forceinline__ float k_sk(float kx, float ky, float kz) {
    return fmaf(kx, kx, fmaf(ky, ky, kz * kz));
}
__device__ __forceinline__ float k_dot(float kx, float ky, float kz,
                                       float qx, float qy, float qz) {
    return fmaf(qx, kx, fmaf(qy, ky, qz * kz));
}
// sk precomputed by pack_kpos with k_sk's exact chain.
__device__ __forceinline__ float pk_d2u(float kx, float ky, float kz, float sk,
                                        float qx, float qy, float qz, float sqn) {
    return fmaf(-2.0f, k_dot(kx, ky, kz, qx, qy, qz), sqn + sk);   // unclamped
}
__device__ __forceinline__ unsigned k_key(float d2u) {
    return __float_as_uint(fmaxf(d2u, 0.0f));
}

__global__ void pack_kpos(const float* __restrict__ k_pos) {
    const int i = blockIdx.x * blockDim.x + threadIdx.x;
    if (i < NKV) {
        const float kx = k_pos[3 * i + 0];
        const float ky = k_pos[3 * i + 1];
        const float kz = k_pos[3 * i + 2];
        g_sx[i] = kx; g_sy[i] = ky; g_sz[i] = kz;
        g_sw[i] = k_sk(kx, ky, kz);
    }
}

// All 512 threads enter. Picks bucket containing the kcur-th smallest;
// results broadcast in sm->s_bucket / sm->s_kneed (valid after return).
__device__ __forceinline__ void pick_bucket(Smem* sm, int kcur, int tid, int lane) {
    int v = 0, incl = 0;
    if (tid < 256) {
        v = (int)sm->hist[tid];
        incl = v;
        #pragma unroll
        for (int o = 1; o < 32; o <<= 1) {
            int y = __shfl_up_sync(0xffffffffu, incl, o);
            if (lane >= o) incl += y;
        }
        if (lane == 31) sm->warpsum[tid >> 5] = incl;
    }
    __syncthreads();
    if (tid < 8) {
        int x = sm->warpsum[tid];
        #pragma unroll
        for (int o = 1; o < 8; o <<= 1) {
            int y = __shfl_up_sync(0xffu, x, o);
            if (tid >= o) x += y;
        }
        sm->warpsum[tid] = x;
    }
    __syncthreads();
    if (tid < 256) {
        const int w   = tid >> 5;
        const int tot = incl + (w ? sm->warpsum[w - 1] : 0);
        const int exc = tot - v;
        if (exc < kcur && tot >= kcur) {   // exactly one thread true
            sm->s_bucket = tid;
            sm->s_kneed  = kcur - exc;
        }
    }
    __syncthreads();
}

__global__ __launch_bounds__(NT, 4)
void sparse_attn_kernel(const float* __restrict__ q_feat,
                        const float* __restrict__ k_feat,
                        const float* __restrict__ v_feat,
                        const float* __restrict__ q_pos,
                        const float* __restrict__ gamma,
                        const float* __restrict__ beta,
                        float* __restrict__ out)
{
    extern __shared__ unsigned char smem_raw[];
    Smem* sm = reinterpret_cast<Smem*>(smem_raw);
    const int tid  = threadIdx.x;
    const int lane = tid & 31;
    const int warp = tid >> 5;
    const int qbase = blockIdx.x * QB;

    const float4* __restrict__ sx4 = (const float4*)g_sx;
    const float4* __restrict__ sy4 = (const float4*)g_sy;
    const float4* __restrict__ sz4 = (const float4*)g_sz;
    const float4* __restrict__ sw4 = (const float4*)g_sw;

    float qx[QB], qy[QB], qz[QB], sqn[QB];
    #pragma unroll
    for (int qi = 0; qi < QB; ++qi) {
        qx[qi] = q_pos[3 * (qbase + qi) + 0];
        qy[qi] = q_pos[3 * (qbase + qi) + 1];
        qz[qi] = q_pos[3 * (qbase + qi) + 2];
        sqn[qi] = fmaf(qx[qi], qx[qi], fmaf(qy[qi], qy[qi], qz[qi] * qz[qi]));
    }
    if (tid == 0) {
        sm->cnt_low[0] = sm->cnt_low[1] = 0;
        sm->cnt_c[0]   = sm->cnt_c[1]   = 0;
    }

    // ---------------- Phase 0: sample keys (first SSAMP points) -------------
    unsigned* samp = (unsigned*)&sm->cand[0][0];   // SSAMP keys/query, overlaid
    if (tid < SSAMP / 4) {                          // 256 threads x 4 points, coalesced
        const float4 X = sx4[tid];
        const float4 Y = sy4[tid];
        const float4 Z = sz4[tid];
        const float4 W = sw4[tid];
        #pragma unroll
        for (int qi = 0; qi < QB; ++qi) {
            uint4 kk;
            kk.x = k_key(pk_d2u(X.x, Y.x, Z.x, W.x, qx[qi], qy[qi], qz[qi], sqn[qi]));
            kk.y = k_key(pk_d2u(X.y, Y.y, Z.y, W.y, qx[qi], qy[qi], qz[qi], sqn[qi]));
            kk.z = k_key(pk_d2u(X.z, Y.z, Z.z, W.z, qx[qi], qy[qi], qz[qi], sqn[qi]));
            kk.w = k_key(pk_d2u(X.w, Y.w, Z.w, W.w, qx[qi], qy[qi], qz[qi], sqn[qi]));
            ((uint4*)samp)[qi * (SSAMP / 4) + tid] = kk;
        }
    }
    __syncthreads();

    // ---------------- Phase 1: 2-pass radix on samples -> threshold t0 ------
    // Upper edge of the 16-bit bucket of the MSEL-th smallest sample key.
    // Superset admission is always safe (exact refine + fallback below).
    float t0f[QB];
    #pragma unroll
    for (int qi = 0; qi < QB; ++qi) {
        unsigned prefval = 0u, prefmask = 0u;
        int kneed = MSEL;
        #pragma unroll
        for (int pass = 0; pass < 2; ++pass) {
            const int shift = 24 - 8 * pass;
            if (tid < 256) sm->hist[tid] = 0u;
            __syncthreads();
            #pragma unroll
            for (int it = 0; it < SSAMP / NT; ++it) {
                const unsigned key = samp[qi * SSAMP + tid + it * NT];
                if ((key & prefmask) == prefval)
                    atomicAdd(&sm->hist[(key >> shift) & 0xFFu], 1u);
            }
            __syncthreads();
            pick_bucket(sm, kneed, tid, lane);
            prefval  |= ((unsigned)sm->s_bucket) << shift;
            kneed     = sm->s_kneed;
            prefmask |= 0xFFu << shift;
            __syncthreads();
        }
        t0f[qi] = __uint_as_float(prefval | 0x0000FFFFu);   // bucket upper edge, >= 0
    }
    __syncthreads();   // done reading samp; cand may now be written

    // ---------------- Phase 2: single full scan (4 points/thread/iter) ------
    // Fully coalesced SoA float4 loads: 4 lines/warp/LDG.
    // (clamped_key <= t0u) <=> (d2u <= t0f) since t0f >= 0.
    #pragma unroll 1
    for (int j = tid; j < NKV / 4; j += NT) {               // 16 iterations
        const float4 X = sx4[j];
        const float4 Y = sy4[j];
        const float4 Z = sz4[j];
        const float4 W = sw4[j];
        #pragma unroll
        for (int qi = 0; qi < QB; ++qi) {
            const float d0 = pk_d2u(X.x, Y.x, Z.x, W.x, qx[qi], qy[qi], qz[qi], sqn[qi]);
            const float d1 = pk_d2u(X.y, Y.y, Z.y, W.y, qx[qi], qy[qi], qz[qi], sqn[qi]);
            const float d2 = pk_d2u(X.z, Y.z, Z.z, W.z, qx[qi], qy[qi], qz[qi], sqn[qi]);
            const float d3 = pk_d2u(X.w, Y.w, Z.w, W.w, qx[qi], qy[qi], qz[qi], sqn[qi]);
            if (d0 <= t0f[qi]) {
                const int p = atomicAdd(&sm->cnt_c[qi], 1);
                if (p < CAP) sm->cand[qi][p] = make_uint2(k_key(d0), (unsigned)(4 * j + 0));
            }
            if (d1 <= t0f[qi]) {
                const int p = atomicAdd(&sm->cnt_c[qi], 1);
                if (p < CAP) sm->cand[qi][p] = make_uint2(k_key(d1), (unsigned)(4 * j + 1));
            }
            if (d2 <= t0f[qi]) {
                const int p = atomicAdd(&sm->cnt_c[qi], 1);
                if (p < CAP) sm->cand[qi][p] = make_uint2(k_key(d2), (unsigned)(4 * j + 2));
            }
            if (d3 <= t0f[qi]) {
                const int p = atomicAdd(&sm->cnt_c[qi], 1);
                if (p < CAP) sm->cand[qi][p] = make_uint2(k_key(d3), (unsigned)(4 * j + 3));
            }
        }
    }
    __syncthreads();

    // ---------------- Phase 3: exact top-KSEL per query ---------------------
    #pragma unroll
    for (int qi = 0; qi < QB; ++qi) {
        const int nc0 = sm->cnt_c[qi];
        unsigned T;
        int kneed;

        if (nc0 >= KSEL && nc0 <= CAP) {
            // ---- refine within <= CAP candidates: full 32-bit radix select --
            const int nc = nc0;
            unsigned prefval = 0u, prefmask = 0u;
            kneed = KSEL;
            #pragma unroll
            for (int pass = 0; pass < 4; ++pass) {
                const int shift = 24 - 8 * pass;
                if (tid < 256) sm->hist[tid] = 0u;
                __syncthreads();
                for (int j = tid; j < nc; j += NT) {
                    const unsigned key = sm->cand[qi][j].x;
                    if ((key & prefmask) == prefval)
                        atomicAdd(&sm->hist[(key >> shift) & 0xFFu], 1u);
                }
                __syncthreads();
                pick_bucket(sm, kneed, tid, lane);
                prefval  |= ((unsigned)sm->s_bucket) << shift;
                kneed     = sm->s_kneed;
                prefmask |= 0xFFu << shift;
                __syncthreads();
            }
            T = prefval;
            // strictly-less keys -> ids (order irrelevant: softmax perm-invariant)
            for (int j = tid; j < nc; j += NT) {
                const uint2 c = sm->cand[qi][j];
                if (c.x < T) {
                    const int p = atomicAdd(&sm->cnt_low[qi], 1);
                    sm->ids[qi][p] = (int)c.y;
                }
            }
            __syncthreads();
            // ties at T: kneed smallest indices (jax top_k stability)
            const int base = sm->cnt_low[qi];
            int last = -1;
            for (int t2 = 0; t2 < kneed; ++t2) {
                int local = 0x7fffffff;
                for (int j = tid; j < nc; j += NT) {
                    const uint2 c = sm->cand[qi][j];
                    if (c.x == T && (int)c.y > last) local = min(local, (int)c.y);
                }
                #pragma unroll
                for (int o = 16; o; o >>= 1)
                    local = min(local, __shfl_xor_sync(0xffffffffu, local, o));
                if (lane == 0) sm->red_min[warp] = local;
                __syncthreads();
                if (tid == 0) {
                    int m = 0x7fffffff;
                    #pragma unroll
                    for (int w = 0; w < NT / 32; ++w) m = min(m, sm->red_min[w]);
                    sm->ids[qi][base + t2] = m;
                    sm->s_m = m;
                }
                __syncthreads();
                last = sm->s_m;
                __syncthreads();
            }
        } else {
            // ---- fallback: exact full-rescan radix select (rare) ------------
            unsigned prefval = 0u, prefmask = 0u;
            kneed = KSEL;
            for (int pass = 0; pass < 4; ++pass) {
                const int shift = 24 - 8 * pass;
                if (tid < 256) sm->hist[tid] = 0u;
                __syncthreads();
                for (int i = tid; i < NKV; i += NT) {
                    const unsigned key = k_key(pk_d2u(g_sx[i], g_sy[i], g_sz[i], g_sw[i],
                                               qx[qi], qy[qi], qz[qi], sqn[qi]));
                    if ((key & prefmask) == prefval)
                        atomicAdd(&sm->hist[(key >> shift) & 0xFFu], 1u);
                }
                __syncthreads();
                pick_bucket(sm, kneed, tid, lane);
                prefval  |= ((unsigned)sm->s_bucket) << shift;
                kneed     = sm->s_kneed;
                prefmask |= 0xFFu << shift;
                __syncthreads();
            }
            T = prefval;
            if (tid == 0) sm->cnt_low[qi] = 0;
            __syncthreads();
            for (int i = tid; i < NKV; i += NT) {
                const unsigned key = k_key(pk_d2u(g_sx[i], g_sy[i], g_sz[i], g_sw[i],
                                           qx[qi], qy[qi], qz[qi], sqn[qi]));
                if (key < T) {
                    const int p = atomicAdd(&sm->cnt_low[qi], 1);
                    sm->ids[qi][p] = i;
                }
            }
            __syncthreads();
            const int base = sm->cnt_low[qi];
            int last = -1;
            for (int t2 = 0; t2 < kneed; ++t2) {
                int local = 0x7fffffff;
                for (int i = tid; i < NKV; i += NT) {
                    const unsigned key = k_key(pk_d2u(g_sx[i], g_sy[i], g_sz[i], g_sw[i],
                                               qx[qi], qy[qi], qz[qi], sqn[qi]));
                    if (key == T && i > last) local = min(local, i);
                }
                #pragma unroll
                for (int o = 16; o; o >>= 1)
                    local = min(local, __shfl_xor_sync(0xffffffffu, local, o));
                if (lane == 0) sm->red_min[warp] = local;
                __syncthreads();
                if (tid == 0) {
                    int m = 0x7fffffff;
                    #pragma unroll
                    for (int w = 0; w < NT / 32; ++w) m = min(m, sm->red_min[w]);
                    sm->ids[qi][base + t2] = m;
                    sm->s_m = m;
                }
                __syncthreads();
                last = sm->s_m;
                __syncthreads();
            }
        }
        __syncthreads();
    }

    // ---------------- Phase 4: attention logits + softmax --------------------
    // q row cached in registers (2 x float4 per lane); warps 0-7 -> q0, 8-15 -> q1.
    const int wq = warp >> 3;
    const int wl = warp & 7;
    {
        const float4* qrow = (const float4*)(q_feat + (long)(qbase + wq) * CDIM);
        const float4 qa = qrow[lane];
        const float4 qb = qrow[lane + 32];
        for (int n = wl; n < KSEL; n += 8) {
            const float4* kr4 = (const float4*)(k_feat + (long)sm->ids[wq][n] * CDIM);
            const float4 ka = kr4[lane];
            const float4 kb = kr4[lane + 32];
            float s = 0.f;
            s = fmaf(qa.x, ka.x, s); s = fmaf(qa.y, ka.y, s);
            s = fmaf(qa.z, ka.z, s); s = fmaf(qa.w, ka.w, s);
            s = fmaf(qb.x, kb.x, s); s = fmaf(qb.y, kb.y, s);
            s = fmaf(qb.z, kb.z, s); s = fmaf(qb.w, kb.w, s);
            #pragma unroll
            for (int o = 16; o; o >>= 1) s += __shfl_xor_sync(0xffffffffu, s, o);
            if (lane == 0) sm->attn[wq][n] = s * 0.0625f;   // C^-0.5 = 1/16
        }
    }
    __syncthreads();

    if ((warp & 7) == 0) {              // warp 0 -> q0, warp 8 -> q1
        const int qi = wq;
        float m = -1e30f;
        for (int n = lane; n < KSEL; n += 32) m = fmaxf(m, sm->attn[qi][n]);
        #pragma unroll
        for (int o = 16; o; o >>= 1) m = fmaxf(m, __shfl_xor_sync(0xffffffffu, m, o));
        float ssum = 0.f;
        for (int n = lane; n < KSEL; n += 32) {
            const float e = __expf(sm->attn[qi][n] - m);
            sm->attn[qi][n] = e;
            ssum += e;
        }
        #pragma unroll
        for (int o = 16; o; o >>= 1) ssum += __shfl_xor_sync(0xffffffffu, ssum, o);
        const float inv = 1.f / ssum;
        for (int n = lane; n < KSEL; n += 32) sm->attn[qi][n] *= inv;
    }
    __syncthreads();

    // ---------------- Phase 5: x = attn @ V (float4, 4 groups/query) --------
    {
        const int qi = tid >> 8;           // query
        const int g  = (tid >> 6) & 3;     // group 0..3 (25 neighbors each)
        const int t  = tid & 63;           // 64 threads x float4 = 256 channels
        float4 acc = make_float4(0.f, 0.f, 0.f, 0.f);
        for (int n = g; n < KSEL; n += 4) {
            const float w  = sm->attn[qi][n];
            const float4 v4 = *(const float4*)(v_feat + (long)sm->ids[qi][n] * CDIM + t * 4);
            acc.x = fmaf(w, v4.x, acc.x);
            acc.y = fmaf(w, v4.y, acc.y);
            acc.z = fmaf(w, v4.z, acc.z);
            acc.w = fmaf(w, v4.w, acc.w);
        }
        sm->part4[qi][g * 64 + t] = acc;
    }
    __syncthreads();

    // ---------------- Phase 6: combine partials; y = 2x; LayerNorm ----------
    {
        const int qi = tid >> 8;
        const int c  = tid & 255;
        const float* pf = (const float*)&sm->part4[qi][0];
        const float y = 2.0f * ((pf[c] + pf[256 + c]) + (pf[512 + c] + pf[768 + c]));

        float s1 = y, s2 = y * y;
        #pragma unroll
        for (int o = 16; o; o >>= 1) {
            s1 += __shfl_xor_sync(0xffffffffu, s1, o);
            s2 += __shfl_xor_sync(0xffffffffu, s2, o);
        }
        if (lane == 0) { sm->red1[warp] = s1; sm->red2[warp] = s2; }
        __syncthreads();
        if ((tid & 255) == 0) {
            float a = 0.f, b = 0.f;
            #pragma unroll
            for (int w = 0; w < 8; ++w) {
                a += sm->red1[qi * 8 + w];
                b += sm->red2[qi * 8 + w];
            }
            sm->s_sum[qi] = a; sm->s_sumsq[qi] = b;
        }
        __syncthreads();
        const float mean = sm->s_sum[qi] * (1.0f / CDIM);
        const float var  = sm->s_sumsq[qi] * (1.0f / CDIM) - mean * mean;
        const float r    = rsqrtf(var + 1e-5f);
        out[(long)(qbase + qi) * CDIM + c] = (y - mean) * r * gamma[c] + beta[c];
    }
}

extern "C" void kernel_launch(void* const* d_in, const int* in_sizes, int n_in,
                              void* d_out, int out_size)
{
    // metadata order: res_feat, q_feat, k_feat, v_feat, q_pos, k_pos, gamma, beta
    // res_feat (d_in[0]) is mathematically dead: full scatter overwrite -> y = 2x.
    const float* q_feat = (const float*)d_in[1];
    const float* k_feat = (const float*)d_in[2];
    const float* v_feat = (const float*)d_in[3];
    const float* q_pos  = (const float*)d_in[4];
    const float* k_pos  = (const float*)d_in[5];
    const float* gamma  = (const float*)d_in[6];
    const float* beta   = (const float*)d_in[7];
    float* out = (float*)d_out;

    (void)in_sizes; (void)n_in; (void)out_size;

    pack_kpos<<<NKV / 256, 256>>>(k_pos);

    cudaFuncSetAttribute(sparse_attn_kernel,
                         cudaFuncAttributeMaxDynamicSharedMemorySize,
                         (int)sizeof(Smem));
    sparse_attn_kernel<<<NQ / QB, NT, sizeof(Smem)>>>(
        q_feat, k_feat, v_feat, q_pos, gamma, beta, out);
}

// round 9
// speedup vs baseline: 1.5146x; 1.1275x over previous
#include <cuda_runtime.h>
#include <cuda_bf16.h>
#include <math.h>

#define NKV   32768
#define NQ    4096
#define CDIM  256
#define KSEL  100
#define NT    512
#define QB    2
#define CAP   2048
#define SSAMP 1024   // sample size for threshold estimation
#define MSEL  16     // 16th-smallest sample key -> threshold (upper bucket edge)

// Spatial grid
#define G       16
#define NCELL   (G * G * G)
#define GRID_LO (-5.5f)
#define CW      (11.0f / G)
#define ICW     (G / 11.0f)
#define MAXCL   512

// Reordered (cell-sorted) SoA point data + original-index map.
__device__ __align__(16) float g_sx[NKV];
__device__ __align__(16) float g_sy[NKV];
__device__ __align__(16) float g_sz[NKV];
__device__ __align__(16) float g_sw[NKV];
__device__ int      g_orig[NKV];
__device__ int      g_cellid[NKV];
__device__ unsigned g_cnt[NCELL];
__device__ unsigned g_cellstart[NCELL + 1];
__device__ unsigned g_cursor[NCELL];
// i.i.d. sample = first SSAMP points in ORIGINAL order (original order is random).
__device__ __align__(16) float g_smx[SSAMP];
__device__ __align__(16) float g_smy[SSAMP];
__device__ __align__(16) float g_smz[SSAMP];
__device__ __align__(16) float g_smw[SSAMP];

struct Smem {
    uint2    cand[QB][CAP];      // 32 KB {key, ORIGINAL idx}; sample keys overlaid
    float4   part4[QB][256];     // 8 KB AV partials
    float    attn[QB][128];
    int      ids[QB][128];       // original indices
    unsigned hist[256];
    unsigned cl_start[MAXCL];    // passing-cell point ranges (reordered space)
    unsigned cl_cnt[MAXCL];
    unsigned cl_base[MAXCL + 1]; // exclusive prefix of cl_cnt
    unsigned warpsum16[16];
    int      warpsum[8];
    int      red_min[16];
    float    red1[16], red2[16];
    int      cnt_low[QB], cnt_c[QB];
    int      s_ncc, s_ovf, s_bucket, s_kneed, s_m;
    float    s_sum[QB], s_sumsq[QB];
};

// Canonical key pieces — identical fmaf chains everywhere => bit-identical keys.
__device__ __forceinline__ float k_sk(float kx, float ky, float kz) {
    return fmaf(kx, kx, fmaf(ky, ky, kz * kz));
}
__device__ __forceinline__ float k_dot(float kx, float ky, float kz,
                                       float qx, float qy, float qz) {
    return fmaf(qx, kx, fmaf(qy, ky, qz * kz));
}
__device__ __forceinline__ float pk_d2u(float kx, float ky, float kz, float sk,
                                        float qx, float qy, float qz, float sqn) {
    return fmaf(-2.0f, k_dot(kx, ky, kz, qx, qy, qz), sqn + sk);   // unclamped
}
__device__ __forceinline__ unsigned k_key(float d2u) {
    return __float_as_uint(fmaxf(d2u, 0.0f));
}
__device__ __forceinline__ int cell_coord(float x) {
    int c = (int)floorf((x - GRID_LO) * ICW);
    return min(G - 1, max(0, c));
}

// ---------------- prepass kernels ----------------
__global__ void prep_zero() {
    const int i = blockIdx.x * blockDim.x + threadIdx.x;
    if (i < NCELL) g_cnt[i] = 0u;
}

__global__ void prep_count(const float* __restrict__ k_pos) {
    const int i = blockIdx.x * blockDim.x + threadIdx.x;
    if (i >= NKV) return;
    const float x = k_pos[3 * i + 0];
    const float y = k_pos[3 * i + 1];
    const float z = k_pos[3 * i + 2];
    const int cell = (cell_coord(z) * G + cell_coord(y)) * G + cell_coord(x);
    g_cellid[i] = cell;
    atomicAdd(&g_cnt[cell], 1u);
    if (i < SSAMP) {
        g_smx[i] = x; g_smy[i] = y; g_smz[i] = z;
        g_smw[i] = k_sk(x, y, z);
    }
}

__global__ void prep_prefix() {      // one block of 512 threads, 8 cells each
    __shared__ unsigned ws[16];
    const int t = threadIdx.x;
    const int lane = t & 31;
    unsigned loc[8];
    unsigned s = 0;
    #pragma unroll
    for (int c = 0; c < 8; ++c) { loc[c] = s; s += g_cnt[t * 8 + c]; }
    unsigned inc = s;
    #pragma unroll
    for (int o = 1; o < 32; o <<= 1) {
        unsigned y = __shfl_up_sync(0xffffffffu, inc, o);
        if (lane >= o) inc += y;
    }
    if (lane == 31) ws[t >> 5] = inc;
    __syncthreads();
    if (t < 16) {
        unsigned x = ws[t];
        #pragma unroll
        for (int o = 1; o < 16; o <<= 1) {
            unsigned y = __shfl_up_sync(0xffffu, x, o);
            if (t >= o) x += y;
        }
        ws[t] = x;
    }
    __syncthreads();
    const unsigned excl = inc - s + ((t >> 5) ? ws[(t >> 5) - 1] : 0u);
    #pragma unroll
    for (int c = 0; c < 8; ++c) {
        g_cellstart[t * 8 + c] = excl + loc[c];
        g_cursor[t * 8 + c]    = excl + loc[c];
    }
    if (t == 511) g_cellstart[NCELL] = excl + s;   // == NKV
}

__global__ void prep_scatter(const float* __restrict__ k_pos) {
    const int i = blockIdx.x * blockDim.x + threadIdx.x;
    if (i >= NKV) return;
    const float x = k_pos[3 * i + 0];
    const float y = k_pos[3 * i + 1];
    const float z = k_pos[3 * i + 2];
    const unsigned p = atomicAdd(&g_cursor[g_cellid[i]], 1u);
    g_sx[p] = x; g_sy[p] = y; g_sz[p] = z;
    g_sw[p] = k_sk(x, y, z);
    g_orig[p] = i;
}

// Cell AABB min squared distance; edge cells unbounded on the outer side so
// clamped out-of-range points can never be wrongly excluded.
__device__ __forceinline__ float cell_min_d2(int ix, int iy, int iz,
                                             float qx, float qy, float qz) {
    float d = 0.f, t;
    float lo = GRID_LO + ix * CW;
    t = 0.f;
    if (ix > 0)     t = fmaxf(t, lo - qx);
    if (ix < G - 1) t = fmaxf(t, qx - (lo + CW));
    d = t * t;
    lo = GRID_LO + iy * CW;
    t = 0.f;
    if (iy > 0)     t = fmaxf(t, lo - qy);
    if (iy < G - 1) t = fmaxf(t, qy - (lo + CW));
    d += t * t;
    lo = GRID_LO + iz * CW;
    t = 0.f;
    if (iz > 0)     t = fmaxf(t, lo - qz);
    if (iz < G - 1) t = fmaxf(t, qz - (lo + CW));
    d += t * t;
    return d;
}

// All 512 threads enter. Picks bucket containing the kcur-th smallest;
// results broadcast in sm->s_bucket / sm->s_kneed (valid after return).
__device__ __forceinline__ void pick_bucket(Smem* sm, int kcur, int tid, int lane) {
    int v = 0, incl = 0;
    if (tid < 256) {
        v = (int)sm->hist[tid];
        incl = v;
        #pragma unroll
        for (int o = 1; o < 32; o <<= 1) {
            int y = __shfl_up_sync(0xffffffffu, incl, o);
            if (lane >= o) incl += y;
        }
        if (lane == 31) sm->warpsum[tid >> 5] = incl;
    }
    __syncthreads();
    if (tid < 8) {
        int x = sm->warpsum[tid];
        #pragma unroll
        for (int o = 1; o < 8; o <<= 1) {
            int y = __shfl_up_sync(0xffu, x, o);
            if (tid >= o) x += y;
        }
        sm->warpsum[tid] = x;
    }
    __syncthreads();
    if (tid < 256) {
        const int w   = tid >> 5;
        const int tot = incl + (w ? sm->warpsum[w - 1] : 0);
        const int exc = tot - v;
        if (exc < kcur && tot >= kcur) {   // exactly one thread true
            sm->s_bucket = tid;
            sm->s_kneed  = kcur - exc;
        }
    }
    __syncthreads();
}

__global__ __launch_bounds__(NT, 4)
void sparse_attn_kernel(const float* __restrict__ q_feat,
                        const float* __restrict__ k_feat,
                        const float* __restrict__ v_feat,
                        const float* __restrict__ q_pos,
                        const float* __restrict__ gamma,
                        const float* __restrict__ beta,
                        float* __restrict__ out)
{
    extern __shared__ unsigned char smem_raw[];
    Smem* sm = reinterpret_cast<Smem*>(smem_raw);
    const int tid  = threadIdx.x;
    const int lane = tid & 31;
    const int warp = tid >> 5;
    const int qbase = blockIdx.x * QB;

    float qx[QB], qy[QB], qz[QB], sqn[QB];
    #pragma unroll
    for (int qi = 0; qi < QB; ++qi) {
        qx[qi] = q_pos[3 * (qbase + qi) + 0];
        qy[qi] = q_pos[3 * (qbase + qi) + 1];
        qz[qi] = q_pos[3 * (qbase + qi) + 2];
        sqn[qi] = fmaf(qx[qi], qx[qi], fmaf(qy[qi], qy[qi], qz[qi] * qz[qi]));
    }
    if (tid == 0) {
        sm->cnt_low[0] = sm->cnt_low[1] = 0;
        sm->cnt_c[0]   = sm->cnt_c[1]   = 0;
    }

    // ---------------- Phase 0: sample keys (i.i.d. copy of first SSAMP orig pts)
    unsigned* samp = (unsigned*)&sm->cand[0][0];   // SSAMP keys/query, overlaid
    if (tid < SSAMP / 4) {
        const float4 X = ((const float4*)g_smx)[tid];
        const float4 Y = ((const float4*)g_smy)[tid];
        const float4 Z = ((const float4*)g_smz)[tid];
        const float4 W = ((const float4*)g_smw)[tid];
        #pragma unroll
        for (int qi = 0; qi < QB; ++qi) {
            uint4 kk;
            kk.x = k_key(pk_d2u(X.x, Y.x, Z.x, W.x, qx[qi], qy[qi], qz[qi], sqn[qi]));
            kk.y = k_key(pk_d2u(X.y, Y.y, Z.y, W.y, qx[qi], qy[qi], qz[qi], sqn[qi]));
            kk.z = k_key(pk_d2u(X.z, Y.z, Z.z, W.z, qx[qi], qy[qi], qz[qi], sqn[qi]));
            kk.w = k_key(pk_d2u(X.w, Y.w, Z.w, W.w, qx[qi], qy[qi], qz[qi], sqn[qi]));
            ((uint4*)samp)[qi * (SSAMP / 4) + tid] = kk;
        }
    }
    __syncthreads();

    // ---------------- Phase 1: 2-pass radix on samples -> threshold t0 ------
    float t0f[QB];
    #pragma unroll
    for (int qi = 0; qi < QB; ++qi) {
        unsigned prefval = 0u, prefmask = 0u;
        int kneed = MSEL;
        #pragma unroll
        for (int pass = 0; pass < 2; ++pass) {
            const int shift = 24 - 8 * pass;
            if (tid < 256) sm->hist[tid] = 0u;
            __syncthreads();
            #pragma unroll
            for (int it = 0; it < SSAMP / NT; ++it) {
                const unsigned key = samp[qi * SSAMP + tid + it * NT];
                if ((key & prefmask) == prefval)
                    atomicAdd(&sm->hist[(key >> shift) & 0xFFu], 1u);
            }
            __syncthreads();
            pick_bucket(sm, kneed, tid, lane);
            prefval  |= ((unsigned)sm->s_bucket) << shift;
            kneed     = sm->s_kneed;
            prefmask |= 0xFFu << shift;
            __syncthreads();
        }
        t0f[qi] = __uint_as_float(prefval | 0x0000FFFFu);   // bucket upper edge, >= 0
    }
    __syncthreads();   // done reading samp; cand may now be written

    // ---------------- Phase 2: grid-pruned scan per query --------------------
    // Admits the EXACT set {d2u <= t0f}: cell gate is a conservative superset
    // (margin 1e-2 >> expansion-formula fp error; edge cells unbounded outward).
    #pragma unroll
    for (int qi = 0; qi < QB; ++qi) {
        const float r2m = t0f[qi] + 1e-2f;
        const float r   = sqrtf(r2m);
        const int ixlo = min(G - 1, max(0, (int)floorf((qx[qi] - r - GRID_LO) * ICW)));
        const int ixhi = min(G - 1, max(0, (int)floorf((qx[qi] + r - GRID_LO) * ICW)));
        const int iylo = min(G - 1, max(0, (int)floorf((qy[qi] - r - GRID_LO) * ICW)));
        const int iyhi = min(G - 1, max(0, (int)floorf((qy[qi] + r - GRID_LO) * ICW)));
        const int izlo = min(G - 1, max(0, (int)floorf((qz[qi] - r - GRID_LO) * ICW)));
        const int izhi = min(G - 1, max(0, (int)floorf((qz[qi] + r - GRID_LO) * ICW)));
        const int nx = ixhi - ixlo + 1, ny = iyhi - iylo + 1, nz = izhi - izlo + 1;
        const int nxy = nx * ny, ncl = nxy * nz;

        if (tid == 0) { sm->s_ncc = 0; sm->s_ovf = 0; }
        __syncthreads();

        for (int c = tid; c < ncl; c += NT) {
            const int iz = izlo + c / nxy;
            const int rem = c - (c / nxy) * nxy;
            const int iy = iylo + rem / nx;
            const int ix = ixlo + rem - (rem / nx) * nx;
            if (cell_min_d2(ix, iy, iz, qx[qi], qy[qi], qz[qi]) <= r2m) {
                const int cell = (iz * G + iy) * G + ix;
                const unsigned s = g_cellstart[cell];
                const unsigned e = g_cellstart[cell + 1];
                if (e > s) {
                    const int p = atomicAdd(&sm->s_ncc, 1);
                    if (p < MAXCL) { sm->cl_start[p] = s; sm->cl_cnt[p] = e - s; }
                    else sm->s_ovf = 1;
                }
            }
        }
        __syncthreads();
        const int ncc = min(sm->s_ncc, MAXCL);
        const int ovf = sm->s_ovf;

        // block exclusive prefix of cl_cnt[0..ncc) -> cl_base
        {
            unsigned v = (tid < ncc) ? sm->cl_cnt[tid] : 0u;
            unsigned inc = v;
            #pragma unroll
            for (int o = 1; o < 32; o <<= 1) {
                unsigned y = __shfl_up_sync(0xffffffffu, inc, o);
                if (lane >= o) inc += y;
            }
            if (lane == 31) sm->warpsum16[warp] = inc;
            __syncthreads();
            if (tid < 16) {
                unsigned x = sm->warpsum16[tid];
                #pragma unroll
                for (int o = 1; o < 16; o <<= 1) {
                    unsigned y = __shfl_up_sync(0xffffu, x, o);
                    if (tid >= o) x += y;
                }
                sm->warpsum16[tid] = x;
            }
            __syncthreads();
            sm->cl_base[tid + 1] = inc + (warp ? sm->warpsum16[warp - 1] : 0u);
            if (tid == 0) sm->cl_base[0] = 0u;
        }
        __syncthreads();

        if (!ovf) {
            const int M = (int)sm->cl_base[ncc];
            int cur = 0;   // monotone cursor into cell list
            for (int v = tid; v < M; v += NT) {
                while ((int)sm->cl_base[cur + 1] <= v) ++cur;
                const int p = (int)sm->cl_start[cur] + (v - (int)sm->cl_base[cur]);
                const float d2u = pk_d2u(g_sx[p], g_sy[p], g_sz[p], g_sw[p],
                                         qx[qi], qy[qi], qz[qi], sqn[qi]);
                if (d2u <= t0f[qi]) {
                    const int pp = atomicAdd(&sm->cnt_c[qi], 1);
                    if (pp < CAP)
                        sm->cand[qi][pp] = make_uint2(k_key(d2u), (unsigned)g_orig[p]);
                }
            }
        }
        // ovf: cnt_c stays 0 -> exact fallback below
        __syncthreads();
    }

    // ---------------- Phase 3: exact top-KSEL per query ---------------------
    #pragma unroll
    for (int qi = 0; qi < QB; ++qi) {
        const int nc0 = sm->cnt_c[qi];
        unsigned T;
        int kneed;

        if (nc0 >= KSEL && nc0 <= CAP) {
            // ---- refine within <= CAP candidates: full 32-bit radix select --
            const int nc = nc0;
            unsigned prefval = 0u, prefmask = 0u;
            kneed = KSEL;
            #pragma unroll
            for (int pass = 0; pass < 4; ++pass) {
                const int shift = 24 - 8 * pass;
                if (tid < 256) sm->hist[tid] = 0u;
                __syncthreads();
                for (int j = tid; j < nc; j += NT) {
                    const unsigned key = sm->cand[qi][j].x;
                    if ((key & prefmask) == prefval)
                        atomicAdd(&sm->hist[(key >> shift) & 0xFFu], 1u);
                }
                __syncthreads();
                pick_bucket(sm, kneed, tid, lane);
                prefval  |= ((unsigned)sm->s_bucket) << shift;
                kneed     = sm->s_kneed;
                prefmask |= 0xFFu << shift;
                __syncthreads();
            }
            T = prefval;
            // strictly-less keys -> ids (order irrelevant: softmax perm-invariant)
            for (int j = tid; j < nc; j += NT) {
                const uint2 c = sm->cand[qi][j];
                if (c.x < T) {
                    const int p = atomicAdd(&sm->cnt_low[qi], 1);
                    sm->ids[qi][p] = (int)c.y;
                }
            }
            __syncthreads();
            // ties at T: kneed smallest ORIGINAL indices (jax top_k stability)
            const int base = sm->cnt_low[qi];
            int last = -1;
            for (int t2 = 0; t2 < kneed; ++t2) {
                int local = 0x7fffffff;
                for (int j = tid; j < nc; j += NT) {
                    const uint2 c = sm->cand[qi][j];
                    if (c.x == T && (int)c.y > last) local = min(local, (int)c.y);
                }
                #pragma unroll
                for (int o = 16; o; o >>= 1)
                    local = min(local, __shfl_xor_sync(0xffffffffu, local, o));
                if (lane == 0) sm->red_min[warp] = local;
                __syncthreads();
                if (tid == 0) {
                    int m = 0x7fffffff;
                    #pragma unroll
                    for (int w = 0; w < NT / 32; ++w) m = min(m, sm->red_min[w]);
                    sm->ids[qi][base + t2] = m;
                    sm->s_m = m;
                }
                __syncthreads();
                last = sm->s_m;
                __syncthreads();
            }
        } else {
            // ---- fallback: exact full-rescan radix select over ALL points ---
            unsigned prefval = 0u, prefmask = 0u;
            kneed = KSEL;
            for (int pass = 0; pass < 4; ++pass) {
                const int shift = 24 - 8 * pass;
                if (tid < 256) sm->hist[tid] = 0u;
                __syncthreads();
                for (int i = tid; i < NKV; i += NT) {
                    const unsigned key = k_key(pk_d2u(g_sx[i], g_sy[i], g_sz[i], g_sw[i],
                                               qx[qi], qy[qi], qz[qi], sqn[qi]));
                    if ((key & prefmask) == prefval)
                        atomicAdd(&sm->hist[(key >> shift) & 0xFFu], 1u);
                }
                __syncthreads();
                pick_bucket(sm, kneed, tid, lane);
                prefval  |= ((unsigned)sm->s_bucket) << shift;
                kneed     = sm->s_kneed;
                prefmask |= 0xFFu << shift;
                __syncthreads();
            }
            T = prefval;
            if (tid == 0) sm->cnt_low[qi] = 0;
            __syncthreads();
            for (int i = tid; i < NKV; i += NT) {
                const unsigned key = k_key(pk_d2u(g_sx[i], g_sy[i], g_sz[i], g_sw[i],
                                           qx[qi], qy[qi], qz[qi], sqn[qi]));
                if (key < T) {
                    const int p = atomicAdd(&sm->cnt_low[qi], 1);
                    sm->ids[qi][p] = g_orig[i];
                }
            }
            __syncthreads();
            const int base = sm->cnt_low[qi];
            int last = -1;
            for (int t2 = 0; t2 < kneed; ++t2) {
                int local = 0x7fffffff;
                for (int i = tid; i < NKV; i += NT) {
                    const unsigned key = k_key(pk_d2u(g_sx[i], g_sy[i], g_sz[i], g_sw[i],
                                               qx[qi], qy[qi], qz[qi], sqn[qi]));
                    const int orig = g_orig[i];
                    if (key == T && orig > last) local = min(local, orig);
                }
                #pragma unroll
                for (int o = 16; o; o >>= 1)
                    local = min(local, __shfl_xor_sync(0xffffffffu, local, o));
                if (lane == 0) sm->red_min[warp] = local;
                __syncthreads();
                if (tid == 0) {
                    int m = 0x7fffffff;
                    #pragma unroll
                    for (int w = 0; w < NT / 32; ++w) m = min(m, sm->red_min[w]);
                    sm->ids[qi][base + t2] = m;
                    sm->s_m = m;
                }
                __syncthreads();
                last = sm->s_m;
                __syncthreads();
            }
        }
        __syncthreads();
    }

    // ---------------- Phase 4: attention logits + softmax --------------------
    // q row cached in registers; warps 0-7 -> q0, 8-15 -> q1.
    const int wq = warp >> 3;
    const int wl = warp & 7;
    {
        const float4* qrow = (const float4*)(q_feat + (long)(qbase + wq) * CDIM);
        const float4 qa = qrow[lane];
        const float4 qb = qrow[lane + 32];
        for (int n = wl; n < KSEL; n += 8) {
            const float4* kr4 = (const float4*)(k_feat + (long)sm->ids[wq][n] * CDIM);
            const float4 ka = kr4[lane];
            const float4 kb = kr4[lane + 32];
            float s = 0.f;
            s = fmaf(qa.x, ka.x, s); s = fmaf(qa.y, ka.y, s);
            s = fmaf(qa.z, ka.z, s); s = fmaf(qa.w, ka.w, s);
            s = fmaf(qb.x, kb.x, s); s = fmaf(qb.y, kb.y, s);
            s = fmaf(qb.z, kb.z, s); s = fmaf(qb.w, kb.w, s);
            #pragma unroll
            for (int o = 16; o; o >>= 1) s += __shfl_xor_sync(0xffffffffu, s, o);
            if (lane == 0) sm->attn[wq][n] = s * 0.0625f;   // C^-0.5 = 1/16
        }
    }
    __syncthreads();

    if ((warp & 7) == 0) {              // warp 0 -> q0, warp 8 -> q1
        const int qi = wq;
        float m = -1e30f;
        for (int n = lane; n < KSEL; n += 32) m = fmaxf(m, sm->attn[qi][n]);
        #pragma unroll
        for (int o = 16; o; o >>= 1) m = fmaxf(m, __shfl_xor_sync(0xffffffffu, m, o));
        float ssum = 0.f;
        for (int n = lane; n < KSEL; n += 32) {
            const float e = __expf(sm->attn[qi][n] - m);
            sm->attn[qi][n] = e;
            ssum += e;
        }
        #pragma unroll
        for (int o = 16; o; o >>= 1) ssum += __shfl_xor_sync(0xffffffffu, ssum, o);
        const float inv = 1.f / ssum;
        for (int n = lane; n < KSEL; n += 32) sm->attn[qi][n] *= inv;
    }
    __syncthreads();

    // ---------------- Phase 5: x = attn @ V (float4, 4 groups/query) --------
    {
        const int qi = tid >> 8;           // query
        const int g  = (tid >> 6) & 3;     // group 0..3 (25 neighbors each)
        const int t  = tid & 63;           // 64 threads x float4 = 256 channels
        float4 acc = make_float4(0.f, 0.f, 0.f, 0.f);
        for (int n = g; n < KSEL; n += 4) {
            const float w  = sm->attn[qi][n];
            const float4 v4 = *(const float4*)(v_feat + (long)sm->ids[qi][n] * CDIM + t * 4);
            acc.x = fmaf(w, v4.x, acc.x);
            acc.y = fmaf(w, v4.y, acc.y);
            acc.z = fmaf(w, v4.z, acc.z);
            acc.w = fmaf(w, v4.w, acc.w);
        }
        sm->part4[qi][g * 64 + t] = acc;
    }
    __syncthreads();

    // ---------------- Phase 6: combine partials; y = 2x; LayerNorm ----------
    {
        const int qi = tid >> 8;
        const int c  = tid & 255;
        const float* pf = (const float*)&sm->part4[qi][0];
        const float y = 2.0f * ((pf[c] + pf[256 + c]) + (pf[512 + c] + pf[768 + c]));

        float s1 = y, s2 = y * y;
        #pragma unroll
        for (int o = 16; o; o >>= 1) {
            s1 += __shfl_xor_sync(0xffffffffu, s1, o);
            s2 += __shfl_xor_sync(0xffffffffu, s2, o);
        }
        if (lane == 0) { sm->red1[warp] = s1; sm->red2[warp] = s2; }
        __syncthreads();
        if ((tid & 255) == 0) {
            float a = 0.f, b = 0.f;
            #pragma unroll
            for (int w = 0; w < 8; ++w) {
                a += sm->red1[qi * 8 + w];
                b += sm->red2[qi * 8 + w];
            }
            sm->s_sum[qi] = a; sm->s_sumsq[qi] = b;
        }
        __syncthreads();
        const float mean = sm->s_sum[qi] * (1.0f / CDIM);
        const float var  = sm->s_sumsq[qi] * (1.0f / CDIM) - mean * mean;
        const float r    = rsqrtf(var + 1e-5f);
        out[(long)(qbase + qi) * CDIM + c] = (y - mean) * r * gamma[c] + beta[c];
    }
}

extern "C" void kernel_launch(void* const* d_in, const int* in_sizes, int n_in,
                              void* d_out, int out_size)
{
    // metadata order: res_feat, q_feat, k_feat, v_feat, q_pos, k_pos, gamma, beta
    // res_feat (d_in[0]) is mathematically dead: full scatter overwrite -> y = 2x.
    const float* q_feat = (const float*)d_in[1];
    const float* k_feat = (const float*)d_in[2];
    const float* v_feat = (const float*)d_in[3];
    const float* q_pos  = (const float*)d_in[4];
    const float* k_pos  = (const float*)d_in[5];
    const float* gamma  = (const float*)d_in[6];
    const float* beta   = (const float*)d_in[7];
    float* out = (float*)d_out;

    (void)in_sizes; (void)n_in; (void)out_size;

    prep_zero<<<NCELL / 256, 256>>>();
    prep_count<<<NKV / 256, 256>>>(k_pos);
    prep_prefix<<<1, 512>>>();
    prep_scatter<<<NKV / 256, 256>>>(k_pos);

    cudaFuncSetAttribute(sparse_attn_kernel,
                         cudaFuncAttributeMaxDynamicSharedMemorySize,
                         (int)sizeof(Smem));
    sparse_attn_kernel<<<NQ / QB, NT, sizeof(Smem)>>>(
        q_feat, k_feat, v_feat, q_pos, gamma, beta, out);
}

// round 10
// speedup vs baseline: 1.7206x; 1.1360x over previous
#include <cuda_runtime.h>
#include <cuda_bf16.h>
#include <math.h>

#define NKV   32768
#define NQ    4096
#define CDIM  256
#define KSEL  100
#define NT    512
#define QB    2
#define CAP   2048
#define SSAMP 1024   // sample size for threshold estimation
#define MSEL  16     // 16th-smallest sample key -> threshold (upper bucket edge)

// Spatial grid
#define G       16
#define NCELL   (G * G * G)
#define GRID_LO (-5.5f)
#define CW      (11.0f / G)
#define ICW     (G / 11.0f)
#define MAXCL   128

// Cell-sorted point data: AoS float4 {x,y,z,|k|^2} -> contiguous lanes = 1 LDG.128/pt.
__device__ __align__(16) float4 g_p4[NKV];
__device__ int      g_orig[NKV];
__device__ int      g_cellid[NKV];
__device__ unsigned g_cnt[NCELL];        // zeroed by prep_prefix after use (invariant)
__device__ unsigned g_cellstart[NCELL + 1];
__device__ unsigned g_cursor[NCELL];
// i.i.d. sample = first SSAMP points in ORIGINAL order.
__device__ __align__(16) float g_smx[SSAMP];
__device__ __align__(16) float g_smy[SSAMP];
__device__ __align__(16) float g_smz[SSAMP];
__device__ __align__(16) float g_smw[SSAMP];

struct Smem {
    uint2    cand[QB][CAP];      // 32 KB {key, ORIGINAL idx}; sample keys overlaid
    float4   part4[QB][256];     // 8 KB AV partials
    float    attn[QB][128];
    int      ids[QB][128];       // original indices
    unsigned hist2[512];         // [query][bin]
    unsigned cl_start2[QB][MAXCL];
    unsigned cl_cnt2[QB][MAXCL];
    unsigned warpsum16[16];
    int      warpsum[8];
    int      red_min[16];
    float    red1[16], red2[16];
    int      cnt_low[QB], cnt_c[QB];
    int      s_ncc[QB], s_ovf[QB];
    int      s_bucket2[QB], s_kneed2[QB];
    int      s_bucket, s_kneed, s_m;
    float    s_sum[QB], s_sumsq[QB];
};

// Canonical key pieces — identical fmaf chains everywhere.
__device__ __forceinline__ float k_sk(float kx, float ky, float kz) {
    return fmaf(kx, kx, fmaf(ky, ky, kz * kz));
}
__device__ __forceinline__ float k_dot(float kx, float ky, float kz,
                                       float qx, float qy, float qz) {
    return fmaf(qx, kx, fmaf(qy, ky, qz * kz));
}
__device__ __forceinline__ float pk_d2u(float kx, float ky, float kz, float sk,
                                        float qx, float qy, float qz, float sqn) {
    return fmaf(-2.0f, k_dot(kx, ky, kz, qx, qy, qz), sqn + sk);   // unclamped
}
__device__ __forceinline__ unsigned k_key(float d2u) {
    return __float_as_uint(fmaxf(d2u, 0.0f));
}
__device__ __forceinline__ int cell_coord(float x) {
    int c = (int)floorf((x - GRID_LO) * ICW);
    return min(G - 1, max(0, c));
}

// ---------------- prepass (3 kernels) ----------------
__global__ void prep_count(const float* __restrict__ k_pos) {
    const int i = blockIdx.x * blockDim.x + threadIdx.x;
    if (i >= NKV) return;
    const float x = k_pos[3 * i + 0];
    const float y = k_pos[3 * i + 1];
    const float z = k_pos[3 * i + 2];
    const int cell = (cell_coord(z) * G + cell_coord(y)) * G + cell_coord(x);
    g_cellid[i] = cell;
    atomicAdd(&g_cnt[cell], 1u);
    if (i < SSAMP) {
        g_smx[i] = x; g_smy[i] = y; g_smz[i] = z;
        g_smw[i] = k_sk(x, y, z);
    }
}

__global__ void prep_prefix() {      // one block of 512 threads, 8 cells each
    __shared__ unsigned ws[16];
    const int t = threadIdx.x;
    const int lane = t & 31;
    unsigned loc[8];
    unsigned s = 0;
    #pragma unroll
    for (int c = 0; c < 8; ++c) { loc[c] = s; s += g_cnt[t * 8 + c]; }
    unsigned inc = s;
    #pragma unroll
    for (int o = 1; o < 32; o <<= 1) {
        unsigned y = __shfl_up_sync(0xffffffffu, inc, o);
        if (lane >= o) inc += y;
    }
    if (lane == 31) ws[t >> 5] = inc;
    __syncthreads();
    if (t < 16) {
        unsigned x = ws[t];
        #pragma unroll
        for (int o = 1; o < 16; o <<= 1) {
            unsigned y = __shfl_up_sync(0xffffu, x, o);
            if (t >= o) x += y;
        }
        ws[t] = x;
    }
    __syncthreads();
    const unsigned excl = inc - s + ((t >> 5) ? ws[(t >> 5) - 1] : 0u);
    #pragma unroll
    for (int c = 0; c < 8; ++c) {
        g_cellstart[t * 8 + c] = excl + loc[c];
        g_cursor[t * 8 + c]    = excl + loc[c];
        g_cnt[t * 8 + c]       = 0u;      // restore zeroed invariant for next replay
    }
    if (t == 511) g_cellstart[NCELL] = excl + s;   // == NKV
}

__global__ void prep_scatter(const float* __restrict__ k_pos) {
    const int i = blockIdx.x * blockDim.x + threadIdx.x;
    if (i >= NKV) return;
    const float x = k_pos[3 * i + 0];
    const float y = k_pos[3 * i + 1];
    const float z = k_pos[3 * i + 2];
    const unsigned p = atomicAdd(&g_cursor[g_cellid[i]], 1u);
    g_p4[p] = make_float4(x, y, z, k_sk(x, y, z));
    g_orig[p] = i;
}

// Cell AABB min squared distance; edge cells unbounded outward.
__device__ __forceinline__ float cell_min_d2(int ix, int iy, int iz,
                                             float qx, float qy, float qz) {
    float d = 0.f, t;
    float lo = GRID_LO + ix * CW;
    t = 0.f;
    if (ix > 0)     t = fmaxf(t, lo - qx);
    if (ix < G - 1) t = fmaxf(t, qx - (lo + CW));
    d = t * t;
    lo = GRID_LO + iy * CW;
    t = 0.f;
    if (iy > 0)     t = fmaxf(t, lo - qy);
    if (iy < G - 1) t = fmaxf(t, qy - (lo + CW));
    d += t * t;
    lo = GRID_LO + iz * CW;
    t = 0.f;
    if (iz > 0)     t = fmaxf(t, lo - qz);
    if (iz < G - 1) t = fmaxf(t, qz - (lo + CW));
    d += t * t;
    return d;
}

// Dual-query bucket pick: threads 0-255 own hist2[0..255] (q0), 256-511 own q1.
// mykcur <= 0 marks this half inactive. Results in s_bucket2[qi]/s_kneed2[qi].
__device__ __forceinline__ void pick_bucket2(Smem* sm, int mykcur, int tid, int lane) {
    const int qi = tid >> 8;
    const int v = (int)sm->hist2[tid];
    int incl = v;
    #pragma unroll
    for (int o = 1; o < 32; o <<= 1) {
        int y = __shfl_up_sync(0xffffffffu, incl, o);
        if (lane >= o) incl += y;
    }
    if (lane == 31) sm->warpsum16[tid >> 5] = incl;
    __syncthreads();
    if (tid < 16) {                       // tid 0-7: q0 warps, 8-15: q1 warps
        int x = (int)sm->warpsum16[tid];
        #pragma unroll
        for (int o = 1; o < 8; o <<= 1) {
            int y = __shfl_up_sync(0xffffu, x, o, 8);   // width-8 segmented
            if ((tid & 7) >= o) x += y;
        }
        sm->warpsum16[tid] = (unsigned)x;
    }
    __syncthreads();
    const int w = (tid >> 5) & 7;
    const int tot = incl + (w ? (int)sm->warpsum16[(qi << 3) + w - 1] : 0);
    const int exc = tot - v;
    if (mykcur > 0 && exc < mykcur && tot >= mykcur) {   // one thread per active qi
        sm->s_bucket2[qi] = tid & 255;
        sm->s_kneed2[qi]  = mykcur - exc;
    }
    __syncthreads();
}

// Whole-block single-query pick (fallback path); hist2[0..255].
__device__ __forceinline__ void pick_bucket(Smem* sm, int kcur, int tid, int lane) {
    int v = 0, incl = 0;
    if (tid < 256) {
        v = (int)sm->hist2[tid];
        incl = v;
        #pragma unroll
        for (int o = 1; o < 32; o <<= 1) {
            int y = __shfl_up_sync(0xffffffffu, incl, o);
            if (lane >= o) incl += y;
        }
        if (lane == 31) sm->warpsum[tid >> 5] = incl;
    }
    __syncthreads();
    if (tid < 8) {
        int x = sm->warpsum[tid];
        #pragma unroll
        for (int o = 1; o < 8; o <<= 1) {
            int y = __shfl_up_sync(0xffu, x, o);
            if (tid >= o) x += y;
        }
        sm->warpsum[tid] = x;
    }
    __syncthreads();
    if (tid < 256) {
        const int w   = tid >> 5;
        const int tot = incl + (w ? sm->warpsum[w - 1] : 0);
        const int exc = tot - v;
        if (exc < kcur && tot >= kcur) {
            sm->s_bucket = tid;
            sm->s_kneed  = kcur - exc;
        }
    }
    __syncthreads();
}

__global__ __launch_bounds__(NT, 4)
void sparse_attn_kernel(const float* __restrict__ q_feat,
                        const float* __restrict__ k_feat,
                        const float* __restrict__ v_feat,
                        const float* __restrict__ q_pos,
                        const float* __restrict__ gamma,
                        const float* __restrict__ beta,
                        float* __restrict__ out)
{
    extern __shared__ unsigned char smem_raw[];
    Smem* sm = reinterpret_cast<Smem*>(smem_raw);
    const int tid  = threadIdx.x;
    const int lane = tid & 31;
    const int warp = tid >> 5;
    const int qbase = blockIdx.x * QB;
    const int qi   = tid >> 8;        // my half's query
    const int t256 = tid & 255;
    const int wh   = (tid >> 5) & 7;  // warp within half

    float qx[QB], qy[QB], qz[QB], sqn[QB];
    #pragma unroll
    for (int q2 = 0; q2 < QB; ++q2) {
        qx[q2] = q_pos[3 * (qbase + q2) + 0];
        qy[q2] = q_pos[3 * (qbase + q2) + 1];
        qz[q2] = q_pos[3 * (qbase + q2) + 2];
        sqn[q2] = fmaf(qx[q2], qx[q2], fmaf(qy[q2], qy[q2], qz[q2] * qz[q2]));
    }
    const float mqx = qi ? qx[1] : qx[0];
    const float mqy = qi ? qy[1] : qy[0];
    const float mqz = qi ? qz[1] : qz[0];
    const float msq = qi ? sqn[1] : sqn[0];

    if (tid == 0) {
        sm->cnt_low[0] = sm->cnt_low[1] = 0;
        sm->cnt_c[0]   = sm->cnt_c[1]   = 0;
    }

    // ---------------- Phase 0: sample keys (both halves in parallel) --------
    unsigned* samp = (unsigned*)&sm->cand[0][0];   // [2][SSAMP] overlaid
    {
        const float4 X = ((const float4*)g_smx)[t256];
        const float4 Y = ((const float4*)g_smy)[t256];
        const float4 Z = ((const float4*)g_smz)[t256];
        const float4 W = ((const float4*)g_smw)[t256];
        uint4 kk;
        kk.x = k_key(pk_d2u(X.x, Y.x, Z.x, W.x, mqx, mqy, mqz, msq));
        kk.y = k_key(pk_d2u(X.y, Y.y, Z.y, W.y, mqx, mqy, mqz, msq));
        kk.z = k_key(pk_d2u(X.z, Y.z, Z.z, W.z, mqx, mqy, mqz, msq));
        kk.w = k_key(pk_d2u(X.w, Y.w, Z.w, W.w, mqx, mqy, mqz, msq));
        ((uint4*)samp)[qi * (SSAMP / 4) + t256] = kk;
    }
    __syncthreads();

    // ---------------- Phase 1: dual 2-pass radix -> thresholds --------------
    float t0f0, t0f1;
    {
        unsigned p0 = 0u, p1 = 0u, prefmask = 0u;
        int k0 = MSEL, k1 = MSEL;
        #pragma unroll
        for (int pass = 0; pass < 2; ++pass) {
            const int shift = 24 - 8 * pass;
            sm->hist2[tid] = 0u;
            __syncthreads();
            const unsigned mypref = qi ? p1 : p0;
            #pragma unroll
            for (int it = 0; it < SSAMP / 256; ++it) {
                const unsigned key = samp[qi * SSAMP + t256 + it * 256];
                if ((key & prefmask) == mypref)
                    atomicAdd(&sm->hist2[(qi << 8) + ((key >> shift) & 0xFFu)], 1u);
            }
            __syncthreads();
            pick_bucket2(sm, qi ? k1 : k0, tid, lane);
            p0 |= ((unsigned)sm->s_bucket2[0]) << shift;
            p1 |= ((unsigned)sm->s_bucket2[1]) << shift;
            k0 = sm->s_kneed2[0];
            k1 = sm->s_kneed2[1];
            prefmask |= 0xFFu << shift;
            __syncthreads();
        }
        t0f0 = __uint_as_float(p0 | 0x0000FFFFu);   // bucket upper edge, >= 0
        t0f1 = __uint_as_float(p1 | 0x0000FFFFu);
    }
    const float mt0 = qi ? t0f1 : t0f0;
    __syncthreads();   // samp dead; cand may be written

    // ---------------- Phase 2: grid-pruned scan (both halves parallel) ------
    // Cell gate is a conservative superset (margin 1e-2 >> fp error of the
    // expansion formula; edge cells unbounded outward) -> admitted set is
    // exactly {d2u <= mt0}. Overflow -> exact fallback.
    {
        const float r2m = mt0 + 1e-2f;
        const float r   = sqrtf(r2m);
        const int ixlo = min(G - 1, max(0, (int)floorf((mqx - r - GRID_LO) * ICW)));
        const int ixhi = min(G - 1, max(0, (int)floorf((mqx + r - GRID_LO) * ICW)));
        const int iylo = min(G - 1, max(0, (int)floorf((mqy - r - GRID_LO) * ICW)));
        const int iyhi = min(G - 1, max(0, (int)floorf((mqy + r - GRID_LO) * ICW)));
        const int izlo = min(G - 1, max(0, (int)floorf((mqz - r - GRID_LO) * ICW)));
        const int izhi = min(G - 1, max(0, (int)floorf((mqz + r - GRID_LO) * ICW)));
        const int nx = ixhi - ixlo + 1, ny = iyhi - iylo + 1;
        const int nxy = nx * ny, ncl = nxy * (izhi - izlo + 1);

        if (t256 == 0) { sm->s_ncc[qi] = 0; sm->s_ovf[qi] = 0; }
        __syncthreads();

        for (int c = t256; c < ncl; c += 256) {
            const int iz = izlo + c / nxy;
            const int rem = c - (c / nxy) * nxy;
            const int iy = iylo + rem / nx;
            const int ix = ixlo + rem - (rem / nx) * nx;
            if (cell_min_d2(ix, iy, iz, mqx, mqy, mqz) <= r2m) {
                const int cell = (iz * G + iy) * G + ix;
                const unsigned s = g_cellstart[cell];
                const unsigned e = g_cellstart[cell + 1];
                if (e > s) {
                    const int p = atomicAdd(&sm->s_ncc[qi], 1);
                    if (p < MAXCL) { sm->cl_start2[qi][p] = s; sm->cl_cnt2[qi][p] = e - s; }
                    else sm->s_ovf[qi] = 1;
                }
            }
        }
        __syncthreads();
        const int ncc = min(sm->s_ncc[qi], MAXCL);
        if (!sm->s_ovf[qi]) {
            // warp-per-cell round robin; lanes stride points (contiguous -> coalesced)
            for (int c = wh; c < ncc; c += 8) {
                const unsigned s = sm->cl_start2[qi][c];
                const unsigned e = s + sm->cl_cnt2[qi][c];
                for (unsigned p = s + lane; p < e; p += 32) {
                    const float4 P = g_p4[p];
                    const float d2u = pk_d2u(P.x, P.y, P.z, P.w, mqx, mqy, mqz, msq);
                    if (d2u <= mt0) {
                        const int pp = atomicAdd(&sm->cnt_c[qi], 1);
                        if (pp < CAP)
                            sm->cand[qi][pp] = make_uint2(k_key(d2u), (unsigned)g_orig[p]);
                    }
                }
            }
        }
        // ovf: cnt_c stays < KSEL (or 0) -> exact fallback below
        __syncthreads();
    }

    // ---------------- Phase 3: exact top-KSEL ---------------------------------
    const int nc0 = sm->cnt_c[0];
    const int nc1 = sm->cnt_c[1];
    const bool fb0 = (nc0 < KSEL || nc0 > CAP);
    const bool fb1 = (nc1 < KSEL || nc1 > CAP);
    const int  mync = qi ? nc1 : nc0;
    const bool myfb = qi ? fb1 : fb0;
    unsigned T0 = 0u, T1 = 0u;
    int kn0 = 0, kn1 = 0;

    if (!fb0 || !fb1) {
        // ---- dual parallel refine: full 32-bit radix over own candidates ----
        unsigned p0 = 0u, p1 = 0u, prefmask = 0u;
        int k0 = KSEL, k1 = KSEL;
        #pragma unroll
        for (int pass = 0; pass < 4; ++pass) {
            const int shift = 24 - 8 * pass;
            sm->hist2[tid] = 0u;
            __syncthreads();
            if (!myfb) {
                const unsigned mypref = qi ? p1 : p0;
                for (int j = t256; j < mync; j += 256) {
                    const unsigned key = sm->cand[qi][j].x;
                    if ((key & prefmask) == mypref)
                        atomicAdd(&sm->hist2[(qi << 8) + ((key >> shift) & 0xFFu)], 1u);
                }
            }
            __syncthreads();
            pick_bucket2(sm, myfb ? 0 : (qi ? k1 : k0), tid, lane);
            if (!fb0) { p0 |= ((unsigned)sm->s_bucket2[0]) << shift; k0 = sm->s_kneed2[0]; }
            if (!fb1) { p1 |= ((unsigned)sm->s_bucket2[1]) << shift; k1 = sm->s_kneed2[1]; }
            prefmask |= 0xFFu << shift;
            __syncthreads();
        }
        T0 = p0; T1 = p1; kn0 = k0; kn1 = k1;
        // gather strictly-less keys in parallel (order irrelevant: softmax
        // is permutation-invariant over neighbors)
        if (!myfb) {
            const unsigned myT = qi ? T1 : T0;
            for (int j = t256; j < mync; j += 256) {
                const uint2 c = sm->cand[qi][j];
                if (c.x < myT) {
                    const int p = atomicAdd(&sm->cnt_low[qi], 1);
                    sm->ids[qi][p] = (int)c.y;
                }
            }
        }
        __syncthreads();
    }

    // ---- ties at T (sequential per query; usually 1 iteration): smallest
    //      ORIGINAL indices (jax top_k stability) ----
    #pragma unroll
    for (int q2 = 0; q2 < QB; ++q2) {
        const bool fb = q2 ? fb1 : fb0;
        if (!fb) {
            const unsigned T = q2 ? T1 : T0;
            const int kneed  = q2 ? kn1 : kn0;
            const int nc     = q2 ? nc1 : nc0;
            const int base   = sm->cnt_low[q2];
            int last = -1;
            for (int t2 = 0; t2 < kneed; ++t2) {
                int local = 0x7fffffff;
                for (int j = tid; j < nc; j += NT) {
                    const uint2 c = sm->cand[q2][j];
                    if (c.x == T && (int)c.y > last) local = min(local, (int)c.y);
                }
                #pragma unroll
                for (int o = 16; o; o >>= 1)
                    local = min(local, __shfl_xor_sync(0xffffffffu, local, o));
                if (lane == 0) sm->red_min[warp] = local;
                __syncthreads();
                if (tid == 0) {
                    int m = 0x7fffffff;
                    #pragma unroll
                    for (int w = 0; w < NT / 32; ++w) m = min(m, sm->red_min[w]);
                    sm->ids[q2][base + t2] = m;
                    sm->s_m = m;
                }
                __syncthreads();
                last = sm->s_m;
                __syncthreads();
            }
        }
    }

    // ---- fallback: exact full-rescan radix select over ALL points (rare) ----
    #pragma unroll
    for (int q2 = 0; q2 < QB; ++q2) {
        const bool fb = q2 ? fb1 : fb0;
        if (fb) {
            unsigned prefval = 0u, prefmask = 0u;
            int kneed = KSEL;
            for (int pass = 0; pass < 4; ++pass) {
                const int shift = 24 - 8 * pass;
                if (tid < 256) sm->hist2[tid] = 0u;
                __syncthreads();
                for (int i = tid; i < NKV; i += NT) {
                    const float4 P = g_p4[i];
                    const unsigned key = k_key(pk_d2u(P.x, P.y, P.z, P.w,
                                               qx[q2], qy[q2], qz[q2], sqn[q2]));
                    if ((key & prefmask) == prefval)
                        atomicAdd(&sm->hist2[(key >> shift) & 0xFFu], 1u);
                }
                __syncthreads();
                pick_bucket(sm, kneed, tid, lane);
                prefval  |= ((unsigned)sm->s_bucket) << shift;
                kneed     = sm->s_kneed;
                prefmask |= 0xFFu << shift;
                __syncthreads();
            }
            const unsigned T = prefval;
            if (tid == 0) sm->cnt_low[q2] = 0;
            __syncthreads();
            for (int i = tid; i < NKV; i += NT) {
                const float4 P = g_p4[i];
                const unsigned key = k_key(pk_d2u(P.x, P.y, P.z, P.w,
                                           qx[q2], qy[q2], qz[q2], sqn[q2]));
                if (key < T) {
                    const int p = atomicAdd(&sm->cnt_low[q2], 1);
                    sm->ids[q2][p] = g_orig[i];
                }
            }
            __syncthreads();
            const int base = sm->cnt_low[q2];
            int last = -1;
            for (int t2 = 0; t2 < kneed; ++t2) {
                int local = 0x7fffffff;
                for (int i = tid; i < NKV; i += NT) {
                    const float4 P = g_p4[i];
                    const unsigned key = k_key(pk_d2u(P.x, P.y, P.z, P.w,
                                               qx[q2], qy[q2], qz[q2], sqn[q2]));
                    const int orig = g_orig[i];
                    if (key == T && orig > last) local = min(local, orig);
                }
                #pragma unroll
                for (int o = 16; o; o >>= 1)
                    local = min(local, __shfl_xor_sync(0xffffffffu, local, o));
                if (lane == 0) sm->red_min[warp] = local;
                __syncthreads();
                if (tid == 0) {
                    int m = 0x7fffffff;
                    #pragma unroll
                    for (int w = 0; w < NT / 32; ++w) m = min(m, sm->red_min[w]);
                    sm->ids[q2][base + t2] = m;
                    sm->s_m = m;
                }
                __syncthreads();
                last = sm->s_m;
                __syncthreads();
            }
        }
    }
    __syncthreads();

    // ---------------- Phase 4: logits (2-way interleaved reductions) ---------
    const int wq = warp >> 3;      // warps 0-7 -> q0, 8-15 -> q1
    const int wl = warp & 7;
    {
        const float4* qrow = (const float4*)(q_feat + (long)(qbase + wq) * CDIM);
        const float4 qa = qrow[lane];
        const float4 qb = qrow[lane + 32];
        for (int n0 = wl; n0 < KSEL; n0 += 16) {
            const int n1 = n0 + 8;
            const float4* kr0 = (const float4*)(k_feat + (long)sm->ids[wq][n0] * CDIM);
            const float4 a0 = kr0[lane], b0 = kr0[lane + 32];
            float s0 = 0.f, s1 = 0.f;
            if (n1 < KSEL) {
                const float4* kr1 = (const float4*)(k_feat + (long)sm->ids[wq][n1] * CDIM);
                const float4 a1 = kr1[lane], b1 = kr1[lane + 32];
                s1 = fmaf(qa.x, a1.x, fmaf(qa.y, a1.y, fmaf(qa.z, a1.z, qa.w * a1.w)));
                s1 = fmaf(qb.x, b1.x, fmaf(qb.y, b1.y, fmaf(qb.z, b1.z, fmaf(qb.w, b1.w, s1))));
            }
            s0 = fmaf(qa.x, a0.x, fmaf(qa.y, a0.y, fmaf(qa.z, a0.z, qa.w * a0.w)));
            s0 = fmaf(qb.x, b0.x, fmaf(qb.y, b0.y, fmaf(qb.z, b0.z, fmaf(qb.w, b0.w, s0))));
            #pragma unroll
            for (int o = 16; o; o >>= 1) {          // independent chains interleave
                s0 += __shfl_xor_sync(0xffffffffu, s0, o);
                s1 += __shfl_xor_sync(0xffffffffu, s1, o);
            }
            if (lane == 0) {
                sm->attn[wq][n0] = s0 * 0.0625f;    // C^-0.5 = 1/16
                if (n1 < KSEL) sm->attn[wq][n1] = s1 * 0.0625f;
            }
        }
    }
    __syncthreads();

    if ((warp & 7) == 0) {              // warp 0 -> q0, warp 8 -> q1
        float m = -1e30f;
        for (int n = lane; n < KSEL; n += 32) m = fmaxf(m, sm->attn[wq][n]);
        #pragma unroll
        for (int o = 16; o; o >>= 1) m = fmaxf(m, __shfl_xor_sync(0xffffffffu, m, o));
        float ssum = 0.f;
        for (int n = lane; n < KSEL; n += 32) {
            const float e = __expf(sm->attn[wq][n] - m);
            sm->attn[wq][n] = e;
            ssum += e;
        }
        #pragma unroll
        for (int o = 16; o; o >>= 1) ssum += __shfl_xor_sync(0xffffffffu, ssum, o);
        const float inv = 1.f / ssum;
        for (int n = lane; n < KSEL; n += 32) sm->attn[wq][n] *= inv;
    }
    __syncthreads();

    // ---------------- Phase 5: x = attn @ V (float4, 4 groups/query) --------
    {
        const int g = (tid >> 6) & 3;     // group 0..3 (25 neighbors each)
        const int t = tid & 63;           // 64 threads x float4 = 256 channels
        float4 acc = make_float4(0.f, 0.f, 0.f, 0.f);
        for (int n = g; n < KSEL; n += 4) {
            const float w  = sm->attn[qi][n];
            const float4 v4 = *(const float4*)(v_feat + (long)sm->ids[qi][n] * CDIM + t * 4);
            acc.x = fmaf(w, v4.x, acc.x);
            acc.y = fmaf(w, v4.y, acc.y);
            acc.z = fmaf(w, v4.z, acc.z);
            acc.w = fmaf(w, v4.w, acc.w);
        }
        sm->part4[qi][g * 64 + t] = acc;
    }
    __syncthreads();

    // ---------------- Phase 6: combine partials; y = 2x; LayerNorm ----------
    {
        const int c = t256;
        const float* pf = (const float*)&sm->part4[qi][0];
        const float y = 2.0f * ((pf[c] + pf[256 + c]) + (pf[512 + c] + pf[768 + c]));

        float s1 = y, s2 = y * y;
        #pragma unroll
        for (int o = 16; o; o >>= 1) {
            s1 += __shfl_xor_sync(0xffffffffu, s1, o);
            s2 += __shfl_xor_sync(0xffffffffu, s2, o);
        }
        if (lane == 0) { sm->red1[warp] = s1; sm->red2[warp] = s2; }
        __syncthreads();
        if (t256 == 0) {
            float a = 0.f, b = 0.f;
            #pragma unroll
            for (int w = 0; w < 8; ++w) {
                a += sm->red1[qi * 8 + w];
                b += sm->red2[qi * 8 + w];
            }
            sm->s_sum[qi] = a; sm->s_sumsq[qi] = b;
        }
        __syncthreads();
        const float mean = sm->s_sum[qi] * (1.0f / CDIM);
        const float var  = sm->s_sumsq[qi] * (1.0f / CDIM) - mean * mean;
        const float r    = rsqrtf(var + 1e-5f);
        out[(long)(qbase + qi) * CDIM + c] = (y - mean) * r * gamma[c] + beta[c];
    }
}

extern "C" void kernel_launch(void* const* d_in, const int* in_sizes, int n_in,
                              void* d_out, int out_size)
{
    // metadata order: res_feat, q_feat, k_feat, v_feat, q_pos, k_pos, gamma, beta
    // res_feat (d_in[0]) is mathematically dead: full scatter overwrite -> y = 2x.
    const float* q_feat = (const float*)d_in[1];
    const float* k_feat = (const float*)d_in[2];
    const float* v_feat = (const float*)d_in[3];
    const float* q_pos  = (const float*)d_in[4];
    const float* k_pos  = (const float*)d_in[5];
    const float* gamma  = (const float*)d_in[6];
    const float* beta   = (const float*)d_in[7];
    float* out = (float*)d_out;

    (void)in_sizes; (void)n_in; (void)out_size;

    // g_cnt starts zeroed (module init) and prep_prefix re-zeros it after use,
    // so the counting pass is correct on every graph replay.
    prep_count<<<NKV / 256, 256>>>(k_pos);
    prep_prefix<<<1, 512>>>();
    prep_scatter<<<NKV / 256, 256>>>(k_pos);

    cudaFuncSetAttribute(sparse_attn_kernel,
                         cudaFuncAttributeMaxDynamicSharedMemorySize,
                         (int)sizeof(Smem));
    sparse_attn_kernel<<<NQ / QB, NT, sizeof(Smem)>>>(
        q_feat, k_feat, v_feat, q_pos, gamma, beta, out);
}

// round 11
// speedup vs baseline: 1.9928x; 1.1582x over previous
#include <cuda_runtime.h>
#include <cuda_bf16.h>
#include <math.h>

#define NKV   32768
#define NQ    4096
#define CDIM  256
#define KSEL  100
#define NT    256
#define CAP   2048
#define SSAMP 1024   // sample size for threshold estimation
#define MSEL  16     // 16th-smallest sample key -> threshold (upper bucket edge)

// Spatial grid
#define G       16
#define NCELL   (G * G * G)
#define GRID_LO (-5.5f)
#define CW      (11.0f / G)
#define ICW     (G / 11.0f)
#define MAXCL   128

// Cell-sorted point data: AoS float4 {x,y,z,|k|^2} -> contiguous lanes = 1 LDG.128/pt.
__device__ __align__(16) float4 g_p4[NKV];
__device__ int      g_orig[NKV];
__device__ int      g_cellid[NKV];
__device__ unsigned g_cnt[NCELL];        // zeroed by prep_prefix after use (invariant)
__device__ unsigned g_cellstart[NCELL + 1];
__device__ unsigned g_cursor[NCELL];
// i.i.d. sample = first SSAMP points in ORIGINAL order.
__device__ __align__(16) float g_smx[SSAMP];
__device__ __align__(16) float g_smy[SSAMP];
__device__ __align__(16) float g_smz[SSAMP];
__device__ __align__(16) float g_smw[SSAMP];

struct Smem {
    uint2    cand[CAP];      // 16 KB {key, ORIGINAL idx}; sample keys overlaid
    float4   part4[256];     // 4 KB AV partials (4 groups x 64 float4)
    float    attn[128];
    int      ids[128];       // original indices
    unsigned hist[256];
    unsigned cl_start[MAXCL];
    unsigned cl_cnt[MAXCL];
    int      warpsum[8];
    int      red_min[8];
    float    red1[8], red2[8];
    int      cnt_low, cnt_c, s_ncc, s_ovf, s_bucket, s_kneed, s_m;
    float    s_sum, s_sumsq;
};

// Canonical key pieces — identical fmaf chains everywhere.
__device__ __forceinline__ float k_sk(float kx, float ky, float kz) {
    return fmaf(kx, kx, fmaf(ky, ky, kz * kz));
}
__device__ __forceinline__ float k_dot(float kx, float ky, float kz,
                                       float qx, float qy, float qz) {
    return fmaf(qx, kx, fmaf(qy, ky, qz * kz));
}
__device__ __forceinline__ float pk_d2u(float kx, float ky, float kz, float sk,
                                        float qx, float qy, float qz, float sqn) {
    return fmaf(-2.0f, k_dot(kx, ky, kz, qx, qy, qz), sqn + sk);   // unclamped
}
__device__ __forceinline__ unsigned k_key(float d2u) {
    return __float_as_uint(fmaxf(d2u, 0.0f));
}
__device__ __forceinline__ int cell_coord(float x) {
    int c = (int)floorf((x - GRID_LO) * ICW);
    return min(G - 1, max(0, c));
}

// ---------------- prepass (3 kernels) ----------------
__global__ void prep_count(const float* __restrict__ k_pos) {
    const int i = blockIdx.x * blockDim.x + threadIdx.x;
    if (i >= NKV) return;
    const float x = k_pos[3 * i + 0];
    const float y = k_pos[3 * i + 1];
    const float z = k_pos[3 * i + 2];
    const int cell = (cell_coord(z) * G + cell_coord(y)) * G + cell_coord(x);
    g_cellid[i] = cell;
    atomicAdd(&g_cnt[cell], 1u);
    if (i < SSAMP) {
        g_smx[i] = x; g_smy[i] = y; g_smz[i] = z;
        g_smw[i] = k_sk(x, y, z);
    }
}

__global__ void prep_prefix() {      // one block of 512 threads, 8 cells each
    __shared__ unsigned ws[16];
    const int t = threadIdx.x;
    const int lane = t & 31;
    unsigned loc[8];
    unsigned s = 0;
    #pragma unroll
    for (int c = 0; c < 8; ++c) { loc[c] = s; s += g_cnt[t * 8 + c]; }
    unsigned inc = s;
    #pragma unroll
    for (int o = 1; o < 32; o <<= 1) {
        unsigned y = __shfl_up_sync(0xffffffffu, inc, o);
        if (lane >= o) inc += y;
    }
    if (lane == 31) ws[t >> 5] = inc;
    __syncthreads();
    if (t < 16) {
        unsigned x = ws[t];
        #pragma unroll
        for (int o = 1; o < 16; o <<= 1) {
            unsigned y = __shfl_up_sync(0xffffu, x, o);
            if (t >= o) x += y;
        }
        ws[t] = x;
    }
    __syncthreads();
    const unsigned excl = inc - s + ((t >> 5) ? ws[(t >> 5) - 1] : 0u);
    #pragma unroll
    for (int c = 0; c < 8; ++c) {
        g_cellstart[t * 8 + c] = excl + loc[c];
        g_cursor[t * 8 + c]    = excl + loc[c];
        g_cnt[t * 8 + c]       = 0u;      // restore zeroed invariant for next replay
    }
    if (t == 511) g_cellstart[NCELL] = excl + s;   // == NKV
}

__global__ void prep_scatter(const float* __restrict__ k_pos) {
    const int i = blockIdx.x * blockDim.x + threadIdx.x;
    if (i >= NKV) return;
    const float x = k_pos[3 * i + 0];
    const float y = k_pos[3 * i + 1];
    const float z = k_pos[3 * i + 2];
    const unsigned p = atomicAdd(&g_cursor[g_cellid[i]], 1u);
    g_p4[p] = make_float4(x, y, z, k_sk(x, y, z));
    g_orig[p] = i;
}

// Cell AABB min squared distance; edge cells unbounded outward.
__device__ __forceinline__ float cell_min_d2(int ix, int iy, int iz,
                                             float qx, float qy, float qz) {
    float d = 0.f, t;
    float lo = GRID_LO + ix * CW;
    t = 0.f;
    if (ix > 0)     t = fmaxf(t, lo - qx);
    if (ix < G - 1) t = fmaxf(t, qx - (lo + CW));
    d = t * t;
    lo = GRID_LO + iy * CW;
    t = 0.f;
    if (iy > 0)     t = fmaxf(t, lo - qy);
    if (iy < G - 1) t = fmaxf(t, qy - (lo + CW));
    d += t * t;
    lo = GRID_LO + iz * CW;
    t = 0.f;
    if (iz > 0)     t = fmaxf(t, lo - qz);
    if (iz < G - 1) t = fmaxf(t, qz - (lo + CW));
    d += t * t;
    return d;
}

// 256 threads, 1 bin each. Result in s_bucket / s_kneed.
__device__ __forceinline__ void pick_bucket(Smem* sm, int kcur, int tid, int lane) {
    const int v = (int)sm->hist[tid];
    int incl = v;
    #pragma unroll
    for (int o = 1; o < 32; o <<= 1) {
        int y = __shfl_up_sync(0xffffffffu, incl, o);
        if (lane >= o) incl += y;
    }
    if (lane == 31) sm->warpsum[tid >> 5] = incl;
    __syncthreads();
    if (tid < 8) {
        int x = sm->warpsum[tid];
        #pragma unroll
        for (int o = 1; o < 8; o <<= 1) {
            int y = __shfl_up_sync(0xffu, x, o);
            if (tid >= o) x += y;
        }
        sm->warpsum[tid] = x;
    }
    __syncthreads();
    const int w   = tid >> 5;
    const int tot = incl + (w ? sm->warpsum[w - 1] : 0);
    const int exc = tot - v;
    if (exc < kcur && tot >= kcur) {   // exactly one thread true
        sm->s_bucket = tid;
        sm->s_kneed  = kcur - exc;
    }
    __syncthreads();
}

__global__ __launch_bounds__(NT, 8)
void sparse_attn_kernel(const float* __restrict__ q_feat,
                        const float* __restrict__ k_feat,
                        const float* __restrict__ v_feat,
                        const float* __restrict__ q_pos,
                        const float* __restrict__ gamma,
                        const float* __restrict__ beta,
                        float* __restrict__ out)
{
    extern __shared__ unsigned char smem_raw[];
    Smem* sm = reinterpret_cast<Smem*>(smem_raw);
    const int tid  = threadIdx.x;
    const int lane = tid & 31;
    const int warp = tid >> 5;     // 0..7
    const int q    = blockIdx.x;

    const float qx = q_pos[3 * q + 0];
    const float qy = q_pos[3 * q + 1];
    const float qz = q_pos[3 * q + 2];
    const float sqn = fmaf(qx, qx, fmaf(qy, qy, qz * qz));

    if (tid == 0) { sm->cnt_low = 0; sm->cnt_c = 0; sm->s_ncc = 0; sm->s_ovf = 0; }

    // ---------------- Phase 0: sample keys (1024 pts, 4/thread, coalesced) --
    unsigned* samp = (unsigned*)&sm->cand[0];   // SSAMP uints overlaid on cand
    {
        const float4 X = ((const float4*)g_smx)[tid];
        const float4 Y = ((const float4*)g_smy)[tid];
        const float4 Z = ((const float4*)g_smz)[tid];
        const float4 W = ((const float4*)g_smw)[tid];
        uint4 kk;
        kk.x = k_key(pk_d2u(X.x, Y.x, Z.x, W.x, qx, qy, qz, sqn));
        kk.y = k_key(pk_d2u(X.y, Y.y, Z.y, W.y, qx, qy, qz, sqn));
        kk.z = k_key(pk_d2u(X.z, Y.z, Z.z, W.z, qx, qy, qz, sqn));
        kk.w = k_key(pk_d2u(X.w, Y.w, Z.w, W.w, qx, qy, qz, sqn));
        ((uint4*)samp)[tid] = kk;
    }
    __syncthreads();

    // ---------------- Phase 1: 2-pass radix on samples -> threshold t0 ------
    float t0f;
    {
        unsigned prefval = 0u, prefmask = 0u;
        int kneed = MSEL;
        #pragma unroll
        for (int pass = 0; pass < 2; ++pass) {
            const int shift = 24 - 8 * pass;
            sm->hist[tid] = 0u;
            __syncthreads();
            #pragma unroll
            for (int it = 0; it < SSAMP / NT; ++it) {
                const unsigned key = samp[tid + it * NT];
                if ((key & prefmask) == prefval)
                    atomicAdd(&sm->hist[(key >> shift) & 0xFFu], 1u);
            }
            __syncthreads();
            pick_bucket(sm, kneed, tid, lane);
            prefval  |= ((unsigned)sm->s_bucket) << shift;
            kneed     = sm->s_kneed;
            prefmask |= 0xFFu << shift;
            __syncthreads();
        }
        t0f = __uint_as_float(prefval | 0x0000FFFFu);   // bucket upper edge, >= 0
    }
    __syncthreads();   // samp dead; cand may be written

    // ---------------- Phase 2: grid-pruned scan ------------------------------
    // Cell gate is a conservative superset (margin 1e-2 >> fp error of the
    // expansion formula; edge cells unbounded outward) -> admitted set is
    // exactly {d2u <= t0f}. Overflow -> exact fallback.
    {
        const float r2m = t0f + 1e-2f;
        const float r   = sqrtf(r2m);
        const int ixlo = min(G - 1, max(0, (int)floorf((qx - r - GRID_LO) * ICW)));
        const int ixhi = min(G - 1, max(0, (int)floorf((qx + r - GRID_LO) * ICW)));
        const int iylo = min(G - 1, max(0, (int)floorf((qy - r - GRID_LO) * ICW)));
        const int iyhi = min(G - 1, max(0, (int)floorf((qy + r - GRID_LO) * ICW)));
        const int izlo = min(G - 1, max(0, (int)floorf((qz - r - GRID_LO) * ICW)));
        const int izhi = min(G - 1, max(0, (int)floorf((qz + r - GRID_LO) * ICW)));
        const int nx = ixhi - ixlo + 1, ny = iyhi - iylo + 1;
        const int nxy = nx * ny, ncl = nxy * (izhi - izlo + 1);

        for (int c = tid; c < ncl; c += NT) {
            const int iz = izlo + c / nxy;
            const int rem = c - (c / nxy) * nxy;
            const int iy = iylo + rem / nx;
            const int ix = ixlo + rem - (rem / nx) * nx;
            if (cell_min_d2(ix, iy, iz, qx, qy, qz) <= r2m) {
                const int cell = (iz * G + iy) * G + ix;
                const unsigned s = g_cellstart[cell];
                const unsigned e = g_cellstart[cell + 1];
                if (e > s) {
                    const int p = atomicAdd(&sm->s_ncc, 1);
                    if (p < MAXCL) { sm->cl_start[p] = s; sm->cl_cnt[p] = e - s; }
                    else sm->s_ovf = 1;
                }
            }
        }
        __syncthreads();
        const int ncc = min(sm->s_ncc, MAXCL);
        if (!sm->s_ovf) {
            // warp-per-cell round robin; lanes stride points (contiguous -> coalesced)
            for (int c = warp; c < ncc; c += 8) {
                const unsigned s = sm->cl_start[c];
                const unsigned e = s + sm->cl_cnt[c];
                for (unsigned p = s + lane; p < e; p += 32) {
                    const float4 P = g_p4[p];
                    const float d2u = pk_d2u(P.x, P.y, P.z, P.w, qx, qy, qz, sqn);
                    if (d2u <= t0f) {
                        const int pp = atomicAdd(&sm->cnt_c, 1);
                        if (pp < CAP)
                            sm->cand[pp] = make_uint2(k_key(d2u), (unsigned)g_orig[p]);
                    }
                }
            }
        }
        __syncthreads();
    }

    // ---------------- Phase 3: exact top-KSEL --------------------------------
    const int nc = sm->cnt_c;
    if (nc >= KSEL && nc <= CAP) {
        // ---- refine within <= CAP candidates: full 32-bit radix select -----
        unsigned prefval = 0u, prefmask = 0u;
        int kneed = KSEL;
        #pragma unroll
        for (int pass = 0; pass < 4; ++pass) {
            const int shift = 24 - 8 * pass;
            sm->hist[tid] = 0u;
            __syncthreads();
            for (int j = tid; j < nc; j += NT) {
                const unsigned key = sm->cand[j].x;
                if ((key & prefmask) == prefval)
                    atomicAdd(&sm->hist[(key >> shift) & 0xFFu], 1u);
            }
            __syncthreads();
            pick_bucket(sm, kneed, tid, lane);
            prefval  |= ((unsigned)sm->s_bucket) << shift;
            kneed     = sm->s_kneed;
            prefmask |= 0xFFu << shift;
            __syncthreads();
        }
        const unsigned T = prefval;
        // strictly-less keys -> ids (order irrelevant: softmax perm-invariant)
        for (int j = tid; j < nc; j += NT) {
            const uint2 c = sm->cand[j];
            if (c.x < T) {
                const int p = atomicAdd(&sm->cnt_low, 1);
                sm->ids[p] = (int)c.y;
            }
        }
        __syncthreads();
        // ties at T: kneed smallest ORIGINAL indices (jax top_k stability)
        const int base = sm->cnt_low;
        int last = -1;
        for (int t2 = 0; t2 < kneed; ++t2) {
            int local = 0x7fffffff;
            for (int j = tid; j < nc; j += NT) {
                const uint2 c = sm->cand[j];
                if (c.x == T && (int)c.y > last) local = min(local, (int)c.y);
            }
            #pragma unroll
            for (int o = 16; o; o >>= 1)
                local = min(local, __shfl_xor_sync(0xffffffffu, local, o));
            if (lane == 0) sm->red_min[warp] = local;
            __syncthreads();
            if (tid == 0) {
                int m = 0x7fffffff;
                #pragma unroll
                for (int w = 0; w < 8; ++w) m = min(m, sm->red_min[w]);
                sm->ids[base + t2] = m;
                sm->s_m = m;
            }
            __syncthreads();
            last = sm->s_m;
            __syncthreads();
        }
    } else {
        // ---- fallback: exact full-rescan radix select over ALL points (rare)
        unsigned prefval = 0u, prefmask = 0u;
        int kneed = KSEL;
        for (int pass = 0; pass < 4; ++pass) {
            const int shift = 24 - 8 * pass;
            sm->hist[tid] = 0u;
            __syncthreads();
            for (int i = tid; i < NKV; i += NT) {
                const float4 P = g_p4[i];
                const unsigned key = k_key(pk_d2u(P.x, P.y, P.z, P.w, qx, qy, qz, sqn));
                if ((key & prefmask) == prefval)
                    atomicAdd(&sm->hist[(key >> shift) & 0xFFu], 1u);
            }
            __syncthreads();
            pick_bucket(sm, kneed, tid, lane);
            prefval  |= ((unsigned)sm->s_bucket) << shift;
            kneed     = sm->s_kneed;
            prefmask |= 0xFFu << shift;
            __syncthreads();
        }
        const unsigned T = prefval;
        if (tid == 0) sm->cnt_low = 0;
        __syncthreads();
        for (int i = tid; i < NKV; i += NT) {
            const float4 P = g_p4[i];
            const unsigned key = k_key(pk_d2u(P.x, P.y, P.z, P.w, qx, qy, qz, sqn));
            if (key < T) {
                const int p = atomicAdd(&sm->cnt_low, 1);
                sm->ids[p] = g_orig[i];
            }
        }
        __syncthreads();
        const int base = sm->cnt_low;
        int last = -1;
        for (int t2 = 0; t2 < kneed; ++t2) {
            int local = 0x7fffffff;
            for (int i = tid; i < NKV; i += NT) {
                const float4 P = g_p4[i];
                const unsigned key = k_key(pk_d2u(P.x, P.y, P.z, P.w, qx, qy, qz, sqn));
                const int orig = g_orig[i];
                if (key == T && orig > last) local = min(local, orig);
            }
            #pragma unroll
            for (int o = 16; o; o >>= 1)
                local = min(local, __shfl_xor_sync(0xffffffffu, local, o));
            if (lane == 0) sm->red_min[warp] = local;
            __syncthreads();
            if (tid == 0) {
                int m = 0x7fffffff;
                #pragma unroll
                for (int w = 0; w < 8; ++w) m = min(m, sm->red_min[w]);
                sm->ids[base + t2] = m;
                sm->s_m = m;
            }
            __syncthreads();
            last = sm->s_m;
            __syncthreads();
        }
    }
    __syncthreads();

    // ---------------- Phase 4: logits (2-way interleaved reductions) ---------
    {
        const float4* qrow = (const float4*)(q_feat + (long)q * CDIM);
        const float4 qa = qrow[lane];
        const float4 qb = qrow[lane + 32];
        for (int n0 = warp; n0 < KSEL; n0 += 16) {
            const int n1 = n0 + 8;
            const float4* kr0 = (const float4*)(k_feat + (long)sm->ids[n0] * CDIM);
            const float4 a0 = kr0[lane], b0 = kr0[lane + 32];
            float s0 = 0.f, s1 = 0.f;
            if (n1 < KSEL) {
                const float4* kr1 = (const float4*)(k_feat + (long)sm->ids[n1] * CDIM);
                const float4 a1 = kr1[lane], b1 = kr1[lane + 32];
                s1 = fmaf(qa.x, a1.x, fmaf(qa.y, a1.y, fmaf(qa.z, a1.z, qa.w * a1.w)));
                s1 = fmaf(qb.x, b1.x, fmaf(qb.y, b1.y, fmaf(qb.z, b1.z, fmaf(qb.w, b1.w, s1))));
            }
            s0 = fmaf(qa.x, a0.x, fmaf(qa.y, a0.y, fmaf(qa.z, a0.z, qa.w * a0.w)));
            s0 = fmaf(qb.x, b0.x, fmaf(qb.y, b0.y, fmaf(qb.z, b0.z, fmaf(qb.w, b0.w, s0))));
            #pragma unroll
            for (int o = 16; o; o >>= 1) {          // independent chains interleave
                s0 += __shfl_xor_sync(0xffffffffu, s0, o);
                s1 += __shfl_xor_sync(0xffffffffu, s1, o);
            }
            if (lane == 0) {
                sm->attn[n0] = s0 * 0.0625f;        // C^-0.5 = 1/16
                if (n1 < KSEL) sm->attn[n1] = s1 * 0.0625f;
            }
        }
    }
    __syncthreads();

    if (warp == 0) {
        float m = -1e30f;
        for (int n = lane; n < KSEL; n += 32) m = fmaxf(m, sm->attn[n]);
        #pragma unroll
        for (int o = 16; o; o >>= 1) m = fmaxf(m, __shfl_xor_sync(0xffffffffu, m, o));
        float ssum = 0.f;
        for (int n = lane; n < KSEL; n += 32) {
            const float e = __expf(sm->attn[n] - m);
            sm->attn[n] = e;
            ssum += e;
        }
        #pragma unroll
        for (int o = 16; o; o >>= 1) ssum += __shfl_xor_sync(0xffffffffu, ssum, o);
        const float inv = 1.f / ssum;
        for (int n = lane; n < KSEL; n += 32) sm->attn[n] *= inv;
    }
    __syncthreads();

    // ---------------- Phase 5: x = attn @ V (float4, 4 groups) ---------------
    {
        const int g = tid >> 6;           // group 0..3 (25 neighbors each)
        const int t = tid & 63;           // 64 threads x float4 = 256 channels
        float4 acc = make_float4(0.f, 0.f, 0.f, 0.f);
        for (int n = g; n < KSEL; n += 4) {
            const float w  = sm->attn[n];
            const float4 v4 = *(const float4*)(v_feat + (long)sm->ids[n] * CDIM + t * 4);
            acc.x = fmaf(w, v4.x, acc.x);
            acc.y = fmaf(w, v4.y, acc.y);
            acc.z = fmaf(w, v4.z, acc.z);
            acc.w = fmaf(w, v4.w, acc.w);
        }
        sm->part4[g * 64 + t] = acc;
    }
    __syncthreads();

    // ---------------- Phase 6: combine partials; y = 2x; LayerNorm -----------
    {
        const int c = tid;
        const float* pf = (const float*)&sm->part4[0];
        const float y = 2.0f * ((pf[c] + pf[256 + c]) + (pf[512 + c] + pf[768 + c]));

        float s1 = y, s2 = y * y;
        #pragma unroll
        for (int o = 16; o; o >>= 1) {
            s1 += __shfl_xor_sync(0xffffffffu, s1, o);
            s2 += __shfl_xor_sync(0xffffffffu, s2, o);
        }
        if (lane == 0) { sm->red1[warp] = s1; sm->red2[warp] = s2; }
        __syncthreads();
        if (tid == 0) {
            float a = 0.f, b = 0.f;
            #pragma unroll
            for (int w = 0; w < 8; ++w) { a += sm->red1[w]; b += sm->red2[w]; }
            sm->s_sum = a; sm->s_sumsq = b;
        }
        __syncthreads();
        const float mean = sm->s_sum * (1.0f / CDIM);
        const float var  = sm->s_sumsq * (1.0f / CDIM) - mean * mean;
        const float r    = rsqrtf(var + 1e-5f);
        out[(long)q * CDIM + c] = (y - mean) * r * gamma[c] + beta[c];
    }
}

extern "C" void kernel_launch(void* const* d_in, const int* in_sizes, int n_in,
                              void* d_out, int out_size)
{
    // metadata order: res_feat, q_feat, k_feat, v_feat, q_pos, k_pos, gamma, beta
    // res_feat (d_in[0]) is mathematically dead: full scatter overwrite -> y = 2x.
    const float* q_feat = (const float*)d_in[1];
    const float* k_feat = (const float*)d_in[2];
    const float* v_feat = (const float*)d_in[3];
    const float* q_pos  = (const float*)d_in[4];
    const float* k_pos  = (const float*)d_in[5];
    const float* gamma  = (const float*)d_in[6];
    const float* beta   = (const float*)d_in[7];
    float* out = (float*)d_out;

    (void)in_sizes; (void)n_in; (void)out_size;

    // g_cnt starts zeroed (module init) and prep_prefix re-zeros it after use,
    // so the counting pass is correct on every graph replay.
    prep_count<<<NKV / 256, 256>>>(k_pos);
    prep_prefix<<<1, 512>>>();
    prep_scatter<<<NKV / 256, 256>>>(k_pos);

    cudaFuncSetAttribute(sparse_attn_kernel,
                         cudaFuncAttributeMaxDynamicSharedMemorySize,
                         (int)sizeof(Smem));
    sparse_attn_kernel<<<NQ, NT, sizeof(Smem)>>>(
        q_feat, k_feat, v_feat, q_pos, gamma, beta, out);
}